// round 1
// baseline (speedup 1.0000x reference)
#include <cuda_runtime.h>

#define B 8
#define T 2048
#define C 1024
#define H 64

typedef unsigned long long ull;

// Scratch for projected q/k/v (no device allocation allowed -> __device__ globals)
__device__ float g_k[B * T * H];
__device__ float g_q[B * T * H];
__device__ float g_v[B * T * H];

__device__ __forceinline__ ull pack2(float a, float b) {
    ull r;
    asm("mov.b64 %0, {%1,%2};" : "=l"(r) : "f"(a), "f"(b));
    return r;
}
__device__ __forceinline__ void unpack2(ull v, float& a, float& b) {
    asm("mov.b64 {%0,%1}, %2;" : "=f"(a), "=f"(b) : "l"(v));
}
// Packed dual-fp32 FMA (Blackwell f32x2 pipe: 2x throughput vs 3-reg FFMA)
__device__ __forceinline__ ull fma2(ull a, ull b, ull c) {
    ull d;
    asm("fma.rn.f32x2 %0, %1, %2, %3;" : "=l"(d) : "l"(a), "l"(b), "l"(c));
    return d;
}

// ---------------------------------------------------------------------------
// Kernel 1: fused QKV projection.
// grid = (B*T/16, 3), block = 256.
// blockIdx.y selects which projection (0=k, 1=q, 2=v).
// Each block: 16 rows of x staged through smem in 256-col chunks; each thread
// owns one output column h (tid&63) across 4 rows (tid>>6 row group).
// ---------------------------------------------------------------------------
__global__ void __launch_bounds__(256) proj_kernel(
    const float* __restrict__ x,
    const float* __restrict__ Wk,
    const float* __restrict__ Wq,
    const float* __restrict__ Wv)
{
    __shared__ float xs[16][256];

    const int which = blockIdx.y;
    const float* __restrict__ W = (which == 0) ? Wk : ((which == 1) ? Wq : Wv);
    float* __restrict__ outp    = (which == 0) ? g_k : ((which == 1) ? g_q : g_v);

    const int row0 = blockIdx.x * 16;
    const int tid  = threadIdx.x;
    const int h    = tid & 63;   // output column
    const int rg   = tid >> 6;   // row group 0..3 (4 rows each)

    ull acc2[4] = {0ull, 0ull, 0ull, 0ull};

    for (int c0 = 0; c0 < C; c0 += 256) {
        __syncthreads();
        // Stage 16 x 256 chunk of x (coalesced float4 loads)
        #pragma unroll
        for (int i = tid; i < 1024; i += 256) {
            int r = i >> 6;
            int cc = (i & 63) << 2;
            *(float4*)&xs[r][cc] =
                *(const float4*)&x[(size_t)(row0 + r) * C + c0 + cc];
        }
        __syncthreads();

        #pragma unroll 8
        for (int c = 0; c < 256; c += 2) {
            float w0 = W[(size_t)(c0 + c) * H + h];
            float w1 = W[(size_t)(c0 + c + 1) * H + h];
            ull w2 = pack2(w0, w1);
            #pragma unroll
            for (int rr = 0; rr < 4; rr++) {
                ull x2 = *(const ull*)&xs[rg * 4 + rr][c];  // ld.shared.b64 broadcast
                acc2[rr] = fma2(x2, w2, acc2[rr]);
            }
        }
    }

    #pragma unroll
    for (int rr = 0; rr < 4; rr++) {
        float a, bq;
        unpack2(acc2[rr], a, bq);
        outp[(size_t)(row0 + rg * 4 + rr) * H + h] = a + bq;
    }
}

// ---------------------------------------------------------------------------
// Kernel 2: causal attention, no-max online softmax (scores bounded ~[-2,2],
// so exp never overflows; softmax(x)=exp(x)/sum(exp(x)) exactly).
// grid = (T/64, B), block = 128. 2 threads per query (32 head dims each),
// pair combined via shfl.xor(1). 64-key K/V tiles in smem.
// Heavy (late) query tiles launch first to balance the causal triangle.
// ---------------------------------------------------------------------------
__global__ void __launch_bounds__(128) attn_kernel(float* __restrict__ out)
{
    __shared__ float Ks[64 * 64];
    __shared__ float Vs[64 * 64];

    const int qt   = (int)gridDim.x - 1 - (int)blockIdx.x;  // heavy tiles first
    const int b    = blockIdx.y;
    const int tid  = threadIdx.x;
    const int qi   = tid >> 1;
    const int half = tid & 1;
    const int t    = qt * 64 + qi;

    const size_t qoff = ((size_t)(b * T + t)) * H + half * 32;

    // Load this thread's 32 q dims, pre-scaled by C^-0.5 = 1/32
    ull q2[16];
    {
        const double2* qp = (const double2*)(g_q + qoff);
        const ull s2 = pack2(0.03125f, 0.03125f);
        #pragma unroll
        for (int j = 0; j < 8; j++) {
            double2 d = qp[j];
            ull a = __double_as_longlong(d.x);
            ull c = __double_as_longlong(d.y);
            asm("mul.rn.f32x2 %0, %0, %1;" : "+l"(a) : "l"(s2));
            asm("mul.rn.f32x2 %0, %0, %1;" : "+l"(c) : "l"(s2));
            q2[2 * j]     = a;
            q2[2 * j + 1] = c;
        }
    }

    ull acc2[16];
    #pragma unroll
    for (int j = 0; j < 16; j++) acc2[j] = 0ull;
    float l = 0.f;

    for (int kt = 0; kt <= qt; kt++) {
        const int s0 = kt * 64;
        __syncthreads();
        {
            const float4* gkp = (const float4*)(g_k + ((size_t)(b * T + s0)) * H);
            const float4* gvp = (const float4*)(g_v + ((size_t)(b * T + s0)) * H);
            #pragma unroll
            for (int i = tid; i < 1024; i += 128) {
                ((float4*)Ks)[i] = gkp[i];
                ((float4*)Vs)[i] = gvp[i];
            }
        }
        __syncthreads();

        const int valid = t - s0;  // keys s with s <= valid are unmasked

        #pragma unroll 2
        for (int s = 0; s < 64; s++) {
            // --- score = (q . k_s) / 32 (scale folded into q) ---
            const double2* kr = (const double2*)(Ks + s * 64 + half * 32);
            ull pa = 0ull, pb = 0ull;  // two chains for ILP
            #pragma unroll
            for (int j = 0; j < 8; j += 2) {
                double2 d0 = kr[j];
                double2 d1 = kr[j + 1];
                pa = fma2(q2[2 * j],     __double_as_longlong(d0.x), pa);
                pb = fma2(q2[2 * j + 1], __double_as_longlong(d0.y), pb);
                pa = fma2(q2[2 * j + 2], __double_as_longlong(d1.x), pa);
                pb = fma2(q2[2 * j + 3], __double_as_longlong(d1.y), pb);
            }
            float a0, a1, b0, b1;
            unpack2(pa, a0, a1);
            unpack2(pb, b0, b1);
            float sc = (a0 + a1) + (b0 + b1);
            sc += __shfl_xor_sync(0xffffffffu, sc, 1);  // combine the two halves

            float p = (s <= valid) ? __expf(sc) : 0.f;
            l += p;

            // --- acc += p * v_s ---
            const ull p2 = pack2(p, p);
            const double2* vr = (const double2*)(Vs + s * 64 + half * 32);
            #pragma unroll
            for (int j = 0; j < 8; j++) {
                double2 d = vr[j];
                acc2[2 * j]     = fma2(p2, __double_as_longlong(d.x), acc2[2 * j]);
                acc2[2 * j + 1] = fma2(p2, __double_as_longlong(d.y), acc2[2 * j + 1]);
            }
        }
    }

    const float inv = 1.f / l;
    float* op = out + qoff;
    #pragma unroll
    for (int j = 0; j < 16; j++) {
        float a, bb;
        unpack2(acc2[j], a, bb);
        float2 w;
        w.x = a * inv;
        w.y = bb * inv;
        *(float2*)(op + 2 * j) = w;
    }
}

extern "C" void kernel_launch(void* const* d_in, const int* in_sizes, int n_in,
                              void* d_out, int out_size)
{
    const float* x  = (const float*)d_in[0];
    const float* Wk = (const float*)d_in[1];
    const float* Wq = (const float*)d_in[2];
    const float* Wv = (const float*)d_in[3];

    proj_kernel<<<dim3(B * T / 16, 3), 256>>>(x, Wk, Wq, Wv);
    attn_kernel<<<dim3(T / 64, B), 128>>>((float*)d_out);
}

// round 2
// speedup vs baseline: 1.8492x; 1.8492x over previous
#include <cuda_runtime.h>

#define B 8
#define T 2048
#define C 1024
#define H 64
#define QTILE 64
#define NQT   (T / QTILE)      // 32 query tiles
#define KCHUNK 256             // keys per attention block (4 tiles of 64)
#define NCH    8               // max chunks per query tile
#define KSTR   68              // padded smem row stride (floats)

typedef unsigned long long ull;

// Scratch (no device allocation allowed -> __device__ globals)
__device__ float g_k[B * T * H];
__device__ float g_q[B * T * H];
__device__ float g_v[B * T * H];
__device__ float g_pacc[B * NQT * NCH * QTILE * H];  // split-K partial acc (33.5MB)
__device__ float g_pl[B * NQT * NCH * QTILE];        // split-K partial l

__device__ __forceinline__ ull pack2(float a, float b) {
    ull r;
    asm("mov.b64 %0, {%1,%2};" : "=l"(r) : "f"(a), "f"(b));
    return r;
}
__device__ __forceinline__ void unpack2(ull v, float& a, float& b) {
    asm("mov.b64 {%0,%1}, %2;" : "=f"(a), "=f"(b) : "l"(v));
}
__device__ __forceinline__ ull fma2(ull a, ull b, ull c) {
    ull d;
    asm("fma.rn.f32x2 %0, %1, %2, %3;" : "=l"(d) : "l"(a), "l"(b), "l"(c));
    return d;
}
__device__ __forceinline__ ull mul2(ull a, ull b) {
    ull d;
    asm("mul.rn.f32x2 %0, %1, %2;" : "=l"(d) : "l"(a), "l"(b));
    return d;
}

// ---------------------------------------------------------------------------
// Kernel 1: fused QKV projection.
// grid = (B*T/32, 3), block = 128. Each block: 32 rows x 64 h.
// Thread owns column h = tid&63 across 16 rows (rg = (tid>>6)*16).
// x staged through smem in 32x128 chunks; W streamed via L1/L2.
// ---------------------------------------------------------------------------
__global__ void __launch_bounds__(128) proj_kernel(
    const float* __restrict__ x,
    const float* __restrict__ Wk,
    const float* __restrict__ Wq,
    const float* __restrict__ Wv)
{
    __shared__ float xs[32][128];

    const int which = blockIdx.y;
    const float* __restrict__ W = (which == 0) ? Wk : ((which == 1) ? Wq : Wv);
    float* __restrict__ outp    = (which == 0) ? g_k : ((which == 1) ? g_q : g_v);

    const int row0 = blockIdx.x * 32;
    const int tid  = threadIdx.x;
    const int h    = tid & 63;
    const int rg   = (tid >> 6) << 4;   // 0 or 16

    ull acc2[16];
    #pragma unroll
    for (int r = 0; r < 16; r++) acc2[r] = 0ull;

    for (int c0 = 0; c0 < C; c0 += 128) {
        __syncthreads();
        // Stage 32 x 128 chunk of x (coalesced float4)
        #pragma unroll
        for (int j = 0; j < 8; j++) {
            int f  = tid + 128 * j;        // 0..1023
            int r  = f >> 5;
            int c4 = (f & 31) << 2;
            *(float4*)&xs[r][c4] =
                *(const float4*)&x[(size_t)(row0 + r) * C + c0 + c4];
        }
        __syncthreads();

        #pragma unroll 4
        for (int cq = 0; cq < 128; cq += 4) {
            const float w0 = W[(size_t)(c0 + cq + 0) * H + h];
            const float w1 = W[(size_t)(c0 + cq + 1) * H + h];
            const float w2 = W[(size_t)(c0 + cq + 2) * H + h];
            const float w3 = W[(size_t)(c0 + cq + 3) * H + h];
            const ull w01 = pack2(w0, w1);
            const ull w23 = pack2(w2, w3);
            #pragma unroll
            for (int r = 0; r < 16; r++) {
                longlong2 xv = *(const longlong2*)&xs[rg + r][cq];  // LDS.128 broadcast
                acc2[r] = fma2((ull)xv.x, w01, acc2[r]);
                acc2[r] = fma2((ull)xv.y, w23, acc2[r]);
            }
        }
    }

    #pragma unroll
    for (int r = 0; r < 16; r++) {
        float a, b2;
        unpack2(acc2[r], a, b2);
        outp[(size_t)(row0 + rg + r) * H + h] = a + b2;
    }
}

// ---------------------------------------------------------------------------
// Kernel 2: split-K causal attention (no-max softmax: scores bounded ~[-2,2]).
// grid = (NCH, NQT, B), block = 128 (2 threads per query x 64 queries).
// Block (chunk, qt, b) processes keys [chunk*256, min(chunk*256+256, (qt+1)*64)),
// writes unnormalized partial acc + partial l. Only the diagonal tile masks.
// ---------------------------------------------------------------------------
__global__ void __launch_bounds__(128) attn_kernel()
{
    const int chunk = blockIdx.x;
    const int qt    = blockIdx.y;
    const int b     = blockIdx.z;

    const int kbeg = chunk * KCHUNK;
    const int klim = (qt + 1) * QTILE;   // exclusive upper bound on keys
    if (kbeg >= klim) return;            // empty split

    __shared__ float Ks[64 * KSTR];
    __shared__ float Vs[64 * KSTR];

    const int tid  = threadIdx.x;
    const int qi   = tid >> 1;
    const int half = tid & 1;
    const int t    = qt * QTILE + qi;
    const int hoff = half * 36;          // bank-shifted half offset in smem rows

    const size_t qoff = ((size_t)(b * T + t)) * H + half * 32;

    // Load 32 q dims, pre-scaled by C^-0.5 = 1/32
    ull q2[16];
    {
        const longlong2* qp = (const longlong2*)(g_q + qoff);
        const ull s2 = pack2(0.03125f, 0.03125f);
        #pragma unroll
        for (int j = 0; j < 8; j++) {
            longlong2 d = qp[j];
            q2[2 * j]     = mul2((ull)d.x, s2);
            q2[2 * j + 1] = mul2((ull)d.y, s2);
        }
    }

    ull acc2[16];
    #pragma unroll
    for (int j = 0; j < 16; j++) acc2[j] = 0ull;
    float l = 0.f;

    const int ntiles = min(4, (klim - kbeg + 63) >> 6);

    for (int kt = 0; kt < ntiles; kt++) {
        const int s0 = kbeg + kt * 64;
        __syncthreads();
        // Stage 64-key K/V tile with padded, bank-shifted layout
        #pragma unroll
        for (int j = 0; j < 8; j++) {
            int f   = tid + 128 * j;            // 0..1023
            int row = f >> 4;
            int c4  = f & 15;
            int dst = row * KSTR + (c4 < 8 ? (c4 << 2) : 36 + ((c4 - 8) << 2));
            const size_t gsrc = ((size_t)(b * T + s0 + row)) * H + (c4 << 2);
            *(float4*)&Ks[dst] = *(const float4*)&g_k[gsrc];
            *(float4*)&Vs[dst] = *(const float4*)&g_v[gsrc];
        }
        __syncthreads();

        const float* kb = Ks + hoff;
        const float* vb = Vs + hoff;
        const bool masked = (s0 == qt * QTILE);   // only the diagonal tile masks

        if (!masked) {
            #pragma unroll 2
            for (int s = 0; s < 64; s++) {
                const longlong2* kr = (const longlong2*)(kb + s * KSTR);
                ull pa = 0ull, pb = 0ull;
                #pragma unroll
                for (int j = 0; j < 8; j++) {
                    longlong2 kk = kr[j];
                    pa = fma2(q2[2 * j],     (ull)kk.x, pa);
                    pb = fma2(q2[2 * j + 1], (ull)kk.y, pb);
                }
                float a0, a1, b0, b1;
                unpack2(pa, a0, a1);
                unpack2(pb, b0, b1);
                float sc = (a0 + a1) + (b0 + b1);
                sc += __shfl_xor_sync(0xffffffffu, sc, 1);
                float p = __expf(sc);
                l += p;
                const ull p2 = pack2(p, p);
                const longlong2* vr = (const longlong2*)(vb + s * KSTR);
                #pragma unroll
                for (int j = 0; j < 8; j++) {
                    longlong2 vv = vr[j];
                    acc2[2 * j]     = fma2(p2, (ull)vv.x, acc2[2 * j]);
                    acc2[2 * j + 1] = fma2(p2, (ull)vv.y, acc2[2 * j + 1]);
                }
            }
        } else {
            #pragma unroll 2
            for (int s = 0; s < 64; s++) {
                const longlong2* kr = (const longlong2*)(kb + s * KSTR);
                ull pa = 0ull, pb = 0ull;
                #pragma unroll
                for (int j = 0; j < 8; j++) {
                    longlong2 kk = kr[j];
                    pa = fma2(q2[2 * j],     (ull)kk.x, pa);
                    pb = fma2(q2[2 * j + 1], (ull)kk.y, pb);
                }
                float a0, a1, b0, b1;
                unpack2(pa, a0, a1);
                unpack2(pb, b0, b1);
                float sc = (a0 + a1) + (b0 + b1);
                sc += __shfl_xor_sync(0xffffffffu, sc, 1);
                float p = (s <= qi) ? __expf(sc) : 0.f;
                l += p;
                const ull p2 = pack2(p, p);
                const longlong2* vr = (const longlong2*)(vb + s * KSTR);
                #pragma unroll
                for (int j = 0; j < 8; j++) {
                    longlong2 vv = vr[j];
                    acc2[2 * j]     = fma2(p2, (ull)vv.x, acc2[2 * j]);
                    acc2[2 * j + 1] = fma2(p2, (ull)vv.y, acc2[2 * j + 1]);
                }
            }
        }
    }

    // Write unnormalized partials
    float* pout = &g_pacc[((((size_t)(b * NQT + qt)) * NCH + chunk) * QTILE + qi) * H + half * 32];
    #pragma unroll
    for (int j = 0; j < 8; j++) {
        longlong2 w;
        w.x = (long long)acc2[2 * j];
        w.y = (long long)acc2[2 * j + 1];
        *(longlong2*)(pout + 4 * j) = w;   // 16B stores of raw fp32 pair bits
    }
    if (half == 0)
        g_pl[(((size_t)(b * NQT + qt)) * NCH + chunk) * QTILE + qi] = l;
}

// ---------------------------------------------------------------------------
// Kernel 3: combine split-K partials. out = sum(acc_c) / sum(l_c).
// grid = (T*H/256, B), block = 256. One output per thread; l broadcast per warp.
// ---------------------------------------------------------------------------
__global__ void __launch_bounds__(256) combine_kernel(float* __restrict__ out)
{
    const int b  = blockIdx.y;
    const int th = blockIdx.x * 256 + threadIdx.x;   // 0..T*H-1
    const int t  = th >> 6;
    const int h  = th & 63;
    const int qt = t >> 6;
    const int qi = t & 63;
    const int nch = (t >> 8) + 1;   // chunks covering keys [0, t]

    const size_t base = ((size_t)(b * NQT + qt)) * NCH;
    float a = 0.f, L = 0.f;
    for (int c = 0; c < nch; c++) {
        a += g_pacc[((base + c) * QTILE + qi) * H + h];
        L += g_pl[(base + c) * QTILE + qi];
    }
    out[((size_t)(b * T + t)) * H + h] = a / L;
}

extern "C" void kernel_launch(void* const* d_in, const int* in_sizes, int n_in,
                              void* d_out, int out_size)
{
    const float* x  = (const float*)d_in[0];
    const float* Wk = (const float*)d_in[1];
    const float* Wq = (const float*)d_in[2];
    const float* Wv = (const float*)d_in[3];

    proj_kernel<<<dim3(B * T / 32, 3), 128>>>(x, Wk, Wq, Wv);
    attn_kernel<<<dim3(NCH, NQT, B), 128>>>();
    combine_kernel<<<dim3(T * H / 256, B), 256>>>((float*)d_out);
}

// round 4
// speedup vs baseline: 2.9894x; 1.6166x over previous
#include <cuda_runtime.h>
#include <cuda_bf16.h>
#include <cstdint>

#define B 8
#define T 2048
#define C 1024
#define H 64
#define QTILE 64
#define NQT   (T / QTILE)
#define KCHUNK 256
#define NCH    8
#define KSTR   68

typedef unsigned long long ull;

// ---------------- scratch (__device__ globals; no allocation allowed) -------
__device__ float g_k[B * T * H];
__device__ float g_q[B * T * H];
__device__ float g_v[B * T * H];
__device__ float g_pacc[B * NQT * NCH * QTILE * H];
__device__ float g_pl[B * NQT * NCH * QTILE];
__device__ __nv_bfloat16 g_xh[B * T * C];       // x hi (bf16)
__device__ __nv_bfloat16 g_xl[B * T * C];       // x lo (bf16 residual)
__device__ __nv_bfloat16 g_bh[3 * H * C];       // W^T hi: [192 n][1024 k]
__device__ __nv_bfloat16 g_bl[3 * H * C];       // W^T lo

// ---------------- helpers ----------------------------------------------------
__device__ __forceinline__ uint32_t smem_u32(const void* p) {
    uint32_t a;
    asm("{ .reg .u64 t; cvta.to.shared.u64 t, %1; cvt.u32.u64 %0, t; }"
        : "=r"(a) : "l"(p));
    return a;
}
__device__ __forceinline__ void cp16(uint32_t saddr, const void* gptr) {
    asm volatile("cp.async.cg.shared.global [%0], [%1], 16;"
                 :: "r"(saddr), "l"(__cvta_generic_to_global(gptr)) : "memory");
}
#define CP_COMMIT() asm volatile("cp.async.commit_group;" ::: "memory")
#define CP_WAIT(n)  asm volatile("cp.async.wait_group %0;" :: "n"(n) : "memory")

__device__ __forceinline__ void ldx4(uint32_t* r, uint32_t addr) {
    asm volatile("ldmatrix.sync.aligned.m8n8.x4.shared.b16 {%0,%1,%2,%3}, [%4];"
                 : "=r"(r[0]), "=r"(r[1]), "=r"(r[2]), "=r"(r[3]) : "r"(addr));
}
__device__ __forceinline__ void mma_bf16(float* c, const uint32_t* a,
                                         uint32_t b0, uint32_t b1) {
    asm volatile(
        "mma.sync.aligned.m16n8k16.row.col.f32.bf16.bf16.f32 "
        "{%0,%1,%2,%3}, {%4,%5,%6,%7}, {%8,%9}, {%0,%1,%2,%3};"
        : "+f"(c[0]), "+f"(c[1]), "+f"(c[2]), "+f"(c[3])
        : "r"(a[0]), "r"(a[1]), "r"(a[2]), "r"(a[3]), "r"(b0), "r"(b1));
}

__device__ __forceinline__ ull pack2(float a, float b) {
    ull r; asm("mov.b64 %0, {%1,%2};" : "=l"(r) : "f"(a), "f"(b)); return r;
}
__device__ __forceinline__ void unpack2(ull v, float& a, float& b) {
    asm("mov.b64 {%0,%1}, %2;" : "=f"(a), "=f"(b) : "l"(v));
}
__device__ __forceinline__ ull fma2(ull a, ull b, ull c) {
    ull d; asm("fma.rn.f32x2 %0, %1, %2, %3;" : "=l"(d) : "l"(a), "l"(b), "l"(c)); return d;
}
__device__ __forceinline__ ull mul2(ull a, ull b) {
    ull d; asm("mul.rn.f32x2 %0, %1, %2;" : "=l"(d) : "l"(a), "l"(b)); return d;
}

// ---------------------------------------------------------------------------
// x -> bf16 hi/lo split
// ---------------------------------------------------------------------------
__global__ void __launch_bounds__(256) convx_kernel(const float* __restrict__ x)
{
    const size_t i = (size_t)blockIdx.x * 256 + threadIdx.x;
    float4 v = ((const float4*)x)[i];
    float f[4] = {v.x, v.y, v.z, v.w};
    ushort4 uh, ul;
    unsigned short* ph = &uh.x;
    unsigned short* pl = &ul.x;
    #pragma unroll
    for (int j = 0; j < 4; j++) {
        __nv_bfloat16 h = __float2bfloat16_rn(f[j]);
        __nv_bfloat16 l = __float2bfloat16_rn(f[j] - __bfloat162float(h));
        ph[j] = __bfloat16_as_ushort(h);
        pl[j] = __bfloat16_as_ushort(l);
    }
    *(ushort4*)&g_xh[4 * i] = uh;
    *(ushort4*)&g_xl[4 * i] = ul;
}

// ---------------------------------------------------------------------------
// W -> transposed bf16 hi/lo: g_b*[ (o*64+n)*1024 + k ] = W_o[k][n]
// ---------------------------------------------------------------------------
__global__ void __launch_bounds__(256) convw_kernel(
    const float* __restrict__ Wk, const float* __restrict__ Wq,
    const float* __restrict__ Wv)
{
    const int idx = blockIdx.x * 256 + threadIdx.x;
    const int o = idx >> 16;
    const int n = (idx >> 10) & 63;
    const int k = idx & 1023;
    const float* W = (o == 0) ? Wk : ((o == 1) ? Wq : Wv);
    float w = W[k * 64 + n];
    __nv_bfloat16 h = __float2bfloat16_rn(w);
    __nv_bfloat16 l = __float2bfloat16_rn(w - __bfloat162float(h));
    g_bh[idx] = h;
    g_bl[idx] = l;
}

// ---------------------------------------------------------------------------
// Projection GEMM on the tensor pipe via mma.sync (HMMA), split-bf16.
// [16384 x 1024] x [1024 x 192], block tile 128x192, warp tile 64x48,
// k chunk 32, cp.async double buffer, 80B-padded smem rows (ldmatrix
// conflict-free).
//
// smem buffer layout (per buffer, 51200 B):
//   Ah: 128 rows * 80B @ 0        Al: @ 10240
//   Bh: 192 rows * 80B @ 20480    Bl: @ 35840
// ---------------------------------------------------------------------------
#define BUFSZ 51200
#define A_LO  10240
#define B_OFF 20480
#define B_LO  15360

__device__ __forceinline__ void stage_chunk(uint32_t smb, int m0, int ch,
                                            int buf, int tid)
{
    const uint32_t base = smb + buf * BUFSZ;
    const int k0 = ch << 5;
    // A hi/lo: 128 rows x 32 bf16 (4 x 16B per row)
    #pragma unroll
    for (int i = 0; i < 2; i++) {
        int idx = tid + 256 * i;            // 0..511
        int r = idx >> 2, q = idx & 3;
        uint32_t sa = base + r * 80 + q * 16;
        size_t g = (size_t)(m0 + r) * 1024 + k0 + q * 8;
        cp16(sa, g_xh + g);
        cp16(sa + A_LO, g_xl + g);
    }
    // B hi/lo: 192 rows x 32 bf16
    #pragma unroll
    for (int i = 0; i < 3; i++) {
        int idx = tid + 256 * i;            // 0..767
        int r = idx >> 2, q = idx & 3;
        uint32_t sb = base + B_OFF + r * 80 + q * 16;
        size_t g = (size_t)r * 1024 + k0 + q * 8;
        cp16(sb, g_bh + g);
        cp16(sb + B_LO, g_bl + g);
    }
}

__global__ void __launch_bounds__(256, 1) proj_gemm_kernel()
{
    extern __shared__ __align__(16) char sm[];
    const uint32_t smb = smem_u32(sm);

    const int tid  = threadIdx.x;
    const int wid  = tid >> 5;
    const int lane = tid & 31;
    const int wr   = wid >> 2;          // warp row: 0..1 (64 M each)
    const int wc   = wid & 3;           // warp col: 0..3 (48 N each)
    const int m0   = blockIdx.x * 128;

    float c[4][6][4];
    #pragma unroll
    for (int mt = 0; mt < 4; mt++)
        #pragma unroll
        for (int nt = 0; nt < 6; nt++)
            #pragma unroll
            for (int e = 0; e < 4; e++) c[mt][nt][e] = 0.f;

    // ldmatrix lane address offsets
    // A (16x16): lanes 0-15 -> rows 0-15 colbyte 0; 16-31 -> rows 0-15 colbyte 16
    const uint32_t aoff = (uint32_t)((wr * 64 + (lane & 15)) * 80 + (lane >> 4) * 16);
    // B (two n8 tiles): g=lane>>3: n-row (lane&7)+(g>>1)*8, kbyte (g&1)*16
    const int bg = lane >> 3;
    const uint32_t boff = (uint32_t)((wc * 48 + (lane & 7) + (bg >> 1) * 8) * 80 + (bg & 1) * 16);

    stage_chunk(smb, m0, 0, 0, tid);
    CP_COMMIT();

    for (int ch = 0; ch < 32; ch++) {
        const int buf = ch & 1;
        if (ch < 31) {
            stage_chunk(smb, m0, ch + 1, buf ^ 1, tid);
            CP_COMMIT();
            CP_WAIT(1);
        } else {
            CP_WAIT(0);
        }
        __syncthreads();

        const uint32_t base = smb + buf * BUFSZ;
        #pragma unroll
        for (int k16 = 0; k16 < 2; k16++) {
            uint32_t ah[4][4], al[4][4], bh[3][4], bl[3][4];
            #pragma unroll
            for (int mt = 0; mt < 4; mt++) {
                uint32_t ad = base + aoff + mt * (16 * 80) + k16 * 32;
                ldx4(ah[mt], ad);
                ldx4(al[mt], ad + A_LO);
            }
            #pragma unroll
            for (int np = 0; np < 3; np++) {
                uint32_t bd = base + B_OFF + boff + np * (16 * 80) + k16 * 32;
                ldx4(bh[np], bd);
                ldx4(bl[np], bd + B_LO);
            }
            #pragma unroll
            for (int mt = 0; mt < 4; mt++) {
                #pragma unroll
                for (int nt = 0; nt < 6; nt++) {
                    const int np = nt >> 1, sel = (nt & 1) * 2;
                    mma_bf16(c[mt][nt], ah[mt], bh[np][sel], bh[np][sel + 1]);
                    mma_bf16(c[mt][nt], ah[mt], bl[np][sel], bl[np][sel + 1]);
                    mma_bf16(c[mt][nt], al[mt], bh[np][sel], bh[np][sel + 1]);
                }
            }
        }
        __syncthreads();
    }

    // Epilogue: scatter accumulators to g_k / g_q / g_v
    #pragma unroll
    for (int mt = 0; mt < 4; mt++) {
        const int row = m0 + wr * 64 + mt * 16 + (lane >> 2);
        #pragma unroll
        for (int nt = 0; nt < 6; nt++) {
            const int ng  = wc * 48 + nt * 8;
            const int mat = ng >> 6;
            const int col = (ng & 63) + 2 * (lane & 3);
            float* dst = (mat == 0) ? g_k : ((mat == 1) ? g_q : g_v);
            float2 w0; w0.x = c[mt][nt][0]; w0.y = c[mt][nt][1];
            float2 w1; w1.x = c[mt][nt][2]; w1.y = c[mt][nt][3];
            *(float2*)&dst[(size_t)row * 64 + col]       = w0;
            *(float2*)&dst[(size_t)(row + 8) * 64 + col] = w1;
        }
    }
}

// ---------------------------------------------------------------------------
// split-K causal attention (unchanged, passing @ ~130us)
// ---------------------------------------------------------------------------
__global__ void __launch_bounds__(128) attn_kernel()
{
    const int chunk = blockIdx.x;
    const int qt    = blockIdx.y;
    const int b     = blockIdx.z;

    const int kbeg = chunk * KCHUNK;
    const int klim = (qt + 1) * QTILE;
    if (kbeg >= klim) return;

    __shared__ float Ks[64 * KSTR];
    __shared__ float Vs[64 * KSTR];

    const int tid  = threadIdx.x;
    const int qi   = tid >> 1;
    const int half = tid & 1;
    const int t    = qt * QTILE + qi;
    const int hoff = half * 36;

    const size_t qoff = ((size_t)(b * T + t)) * H + half * 32;

    ull q2[16];
    {
        const longlong2* qp = (const longlong2*)(g_q + qoff);
        const ull s2 = pack2(0.03125f, 0.03125f);
        #pragma unroll
        for (int j = 0; j < 8; j++) {
            longlong2 d = qp[j];
            q2[2 * j]     = mul2((ull)d.x, s2);
            q2[2 * j + 1] = mul2((ull)d.y, s2);
        }
    }

    ull acc2[16];
    #pragma unroll
    for (int j = 0; j < 16; j++) acc2[j] = 0ull;
    float l = 0.f;

    const int ntiles = min(4, (klim - kbeg + 63) >> 6);

    for (int kt = 0; kt < ntiles; kt++) {
        const int s0 = kbeg + kt * 64;
        __syncthreads();
        #pragma unroll
        for (int j = 0; j < 8; j++) {
            int f   = tid + 128 * j;
            int row = f >> 4;
            int c4  = f & 15;
            int dst = row * KSTR + (c4 < 8 ? (c4 << 2) : 36 + ((c4 - 8) << 2));
            const size_t gsrc = ((size_t)(b * T + s0 + row)) * H + (c4 << 2);
            *(float4*)&Ks[dst] = *(const float4*)&g_k[gsrc];
            *(float4*)&Vs[dst] = *(const float4*)&g_v[gsrc];
        }
        __syncthreads();

        const float* kb = Ks + hoff;
        const float* vb = Vs + hoff;
        const bool masked = (s0 == qt * QTILE);

        if (!masked) {
            #pragma unroll 2
            for (int s = 0; s < 64; s++) {
                const longlong2* kr = (const longlong2*)(kb + s * KSTR);
                ull pa = 0ull, pb = 0ull;
                #pragma unroll
                for (int j = 0; j < 8; j++) {
                    longlong2 kk = kr[j];
                    pa = fma2(q2[2 * j],     (ull)kk.x, pa);
                    pb = fma2(q2[2 * j + 1], (ull)kk.y, pb);
                }
                float a0, a1, b0, b1;
                unpack2(pa, a0, a1);
                unpack2(pb, b0, b1);
                float sc = (a0 + a1) + (b0 + b1);
                sc += __shfl_xor_sync(0xffffffffu, sc, 1);
                float p = __expf(sc);
                l += p;
                const ull p2 = pack2(p, p);
                const longlong2* vr = (const longlong2*)(vb + s * KSTR);
                #pragma unroll
                for (int j = 0; j < 8; j++) {
                    longlong2 vv = vr[j];
                    acc2[2 * j]     = fma2(p2, (ull)vv.x, acc2[2 * j]);
                    acc2[2 * j + 1] = fma2(p2, (ull)vv.y, acc2[2 * j + 1]);
                }
            }
        } else {
            #pragma unroll 2
            for (int s = 0; s < 64; s++) {
                const longlong2* kr = (const longlong2*)(kb + s * KSTR);
                ull pa = 0ull, pb = 0ull;
                #pragma unroll
                for (int j = 0; j < 8; j++) {
                    longlong2 kk = kr[j];
                    pa = fma2(q2[2 * j],     (ull)kk.x, pa);
                    pb = fma2(q2[2 * j + 1], (ull)kk.y, pb);
                }
                float a0, a1, b0, b1;
                unpack2(pa, a0, a1);
                unpack2(pb, b0, b1);
                float sc = (a0 + a1) + (b0 + b1);
                sc += __shfl_xor_sync(0xffffffffu, sc, 1);
                float p = (s <= qi) ? __expf(sc) : 0.f;
                l += p;
                const ull p2 = pack2(p, p);
                const longlong2* vr = (const longlong2*)(vb + s * KSTR);
                #pragma unroll
                for (int j = 0; j < 8; j++) {
                    longlong2 vv = vr[j];
                    acc2[2 * j]     = fma2(p2, (ull)vv.x, acc2[2 * j]);
                    acc2[2 * j + 1] = fma2(p2, (ull)vv.y, acc2[2 * j + 1]);
                }
            }
        }
    }

    float* pout = &g_pacc[((((size_t)(b * NQT + qt)) * NCH + chunk) * QTILE + qi) * H + half * 32];
    #pragma unroll
    for (int j = 0; j < 8; j++) {
        longlong2 w;
        w.x = (long long)acc2[2 * j];
        w.y = (long long)acc2[2 * j + 1];
        *(longlong2*)(pout + 4 * j) = w;
    }
    if (half == 0)
        g_pl[(((size_t)(b * NQT + qt)) * NCH + chunk) * QTILE + qi] = l;
}

__global__ void __launch_bounds__(256) combine_kernel(float* __restrict__ out)
{
    const int b  = blockIdx.y;
    const int th = blockIdx.x * 256 + threadIdx.x;
    const int t  = th >> 6;
    const int h  = th & 63;
    const int qt = t >> 6;
    const int qi = t & 63;
    const int nch = (t >> 8) + 1;

    const size_t base = ((size_t)(b * NQT + qt)) * NCH;
    float a = 0.f, L = 0.f;
    for (int c = 0; c < nch; c++) {
        a += g_pacc[((base + c) * QTILE + qi) * H + h];
        L += g_pl[(base + c) * QTILE + qi];
    }
    out[((size_t)(b * T + t)) * H + h] = a / L;
}

extern "C" void kernel_launch(void* const* d_in, const int* in_sizes, int n_in,
                              void* d_out, int out_size)
{
    const float* x  = (const float*)d_in[0];
    const float* Wk = (const float*)d_in[1];
    const float* Wq = (const float*)d_in[2];
    const float* Wv = (const float*)d_in[3];

    cudaFuncSetAttribute(proj_gemm_kernel,
                         cudaFuncAttributeMaxDynamicSharedMemorySize, 2 * BUFSZ);

    convx_kernel<<<16384, 256>>>(x);
    convw_kernel<<<768, 256>>>(Wk, Wq, Wv);
    proj_gemm_kernel<<<128, 256, 2 * BUFSZ>>>();
    attn_kernel<<<dim3(NCH, NQT, B), 128>>>();
    combine_kernel<<<dim3(T * H / 256, B), 256>>>((float*)d_out);
}

// round 5
// speedup vs baseline: 5.6994x; 1.9065x over previous
#include <cuda_runtime.h>
#include <cuda_bf16.h>
#include <cstdint>

#define B 8
#define T 2048
#define C 1024
#define H 64
#define QTILE 64
#define NQT   (T / QTILE)
#define KCHUNK 256
#define NCH    8

typedef unsigned long long ull;

// ---------------- scratch (__device__ globals; no allocation allowed) -------
__device__ float g_pacc[B * NQT * NCH * QTILE * H];
__device__ float g_pl[B * NQT * NCH * QTILE];
__device__ __nv_bfloat16 g_xh[B * T * C];
__device__ __nv_bfloat16 g_xl[B * T * C];
__device__ __nv_bfloat16 g_bh[3 * H * C];
__device__ __nv_bfloat16 g_bl[3 * H * C];
// projected q/k/v as bf16 hi/lo (q pre-scaled by 1/32)
__device__ __nv_bfloat16 g_qh[B * T * H];
__device__ __nv_bfloat16 g_ql[B * T * H];
__device__ __nv_bfloat16 g_kh[B * T * H];
__device__ __nv_bfloat16 g_kl[B * T * H];
__device__ __nv_bfloat16 g_vh[B * T * H];
__device__ __nv_bfloat16 g_vl[B * T * H];

// ---------------- helpers ----------------------------------------------------
__device__ __forceinline__ uint32_t smem_u32(const void* p) {
    uint32_t a;
    asm("{ .reg .u64 t; cvta.to.shared.u64 t, %1; cvt.u32.u64 %0, t; }"
        : "=r"(a) : "l"(p));
    return a;
}
__device__ __forceinline__ void cp16(uint32_t saddr, const void* gptr) {
    asm volatile("cp.async.cg.shared.global [%0], [%1], 16;"
                 :: "r"(saddr), "l"(__cvta_generic_to_global(gptr)) : "memory");
}
#define CP_COMMIT() asm volatile("cp.async.commit_group;" ::: "memory")
#define CP_WAIT(n)  asm volatile("cp.async.wait_group %0;" :: "n"(n) : "memory")

__device__ __forceinline__ void ldx4(uint32_t* r, uint32_t addr) {
    asm volatile("ldmatrix.sync.aligned.m8n8.x4.shared.b16 {%0,%1,%2,%3}, [%4];"
                 : "=r"(r[0]), "=r"(r[1]), "=r"(r[2]), "=r"(r[3]) : "r"(addr));
}
__device__ __forceinline__ void ldx4t(uint32_t* r, uint32_t addr) {
    asm volatile("ldmatrix.sync.aligned.m8n8.x4.trans.shared.b16 {%0,%1,%2,%3}, [%4];"
                 : "=r"(r[0]), "=r"(r[1]), "=r"(r[2]), "=r"(r[3]) : "r"(addr));
}
__device__ __forceinline__ void mma_bf16(float* c, const uint32_t* a,
                                         uint32_t b0, uint32_t b1) {
    asm volatile(
        "mma.sync.aligned.m16n8k16.row.col.f32.bf16.bf16.f32 "
        "{%0,%1,%2,%3}, {%4,%5,%6,%7}, {%8,%9}, {%0,%1,%2,%3};"
        : "+f"(c[0]), "+f"(c[1]), "+f"(c[2]), "+f"(c[3])
        : "r"(a[0]), "r"(a[1]), "r"(a[2]), "r"(a[3]), "r"(b0), "r"(b1));
}
// pack two fp32 -> bf16x2 (lo in low half)
__device__ __forceinline__ uint32_t packbf(float lo, float hi) {
    uint32_t r;
    asm("cvt.rn.bf16x2.f32 %0, %1, %2;" : "=r"(r) : "f"(hi), "f"(lo));
    return r;
}
// split two fp32 into hi bf16x2 + residual bf16x2
__device__ __forceinline__ void split2(float f0, float f1, uint32_t& ph, uint32_t& pl) {
    ph = packbf(f0, f1);
    float h0 = __bfloat162float(__ushort_as_bfloat16((unsigned short)(ph & 0xffff)));
    float h1 = __bfloat162float(__ushort_as_bfloat16((unsigned short)(ph >> 16)));
    pl = packbf(f0 - h0, f1 - h1);
}

// ---------------------------------------------------------------------------
// x -> bf16 hi/lo split
// ---------------------------------------------------------------------------
__global__ void __launch_bounds__(256) convx_kernel(const float* __restrict__ x)
{
    const size_t i = (size_t)blockIdx.x * 256 + threadIdx.x;
    float4 v = ((const float4*)x)[i];
    float f[4] = {v.x, v.y, v.z, v.w};
    ushort4 uh, ul;
    unsigned short* ph = &uh.x;
    unsigned short* pl = &ul.x;
    #pragma unroll
    for (int j = 0; j < 4; j++) {
        __nv_bfloat16 h = __float2bfloat16_rn(f[j]);
        __nv_bfloat16 l = __float2bfloat16_rn(f[j] - __bfloat162float(h));
        ph[j] = __bfloat16_as_ushort(h);
        pl[j] = __bfloat16_as_ushort(l);
    }
    *(ushort4*)&g_xh[4 * i] = uh;
    *(ushort4*)&g_xl[4 * i] = ul;
}

// ---------------------------------------------------------------------------
// W -> transposed bf16 hi/lo
// ---------------------------------------------------------------------------
__global__ void __launch_bounds__(256) convw_kernel(
    const float* __restrict__ Wk, const float* __restrict__ Wq,
    const float* __restrict__ Wv)
{
    const int idx = blockIdx.x * 256 + threadIdx.x;
    const int o = idx >> 16;
    const int n = (idx >> 10) & 63;
    const int k = idx & 1023;
    const float* W = (o == 0) ? Wk : ((o == 1) ? Wq : Wv);
    float w = W[k * 64 + n];
    __nv_bfloat16 h = __float2bfloat16_rn(w);
    __nv_bfloat16 l = __float2bfloat16_rn(w - __bfloat162float(h));
    g_bh[idx] = h;
    g_bl[idx] = l;
}

// ---------------------------------------------------------------------------
// Projection GEMM (HMMA, split-bf16). Epilogue emits bf16 hi/lo q/k/v,
// with the 1/32 score scale folded into q.
// ---------------------------------------------------------------------------
#define BUFSZ 51200
#define A_LO  10240
#define B_OFF 20480
#define B_LO  15360

__device__ __forceinline__ void stage_chunk(uint32_t smb, int m0, int ch,
                                            int buf, int tid)
{
    const uint32_t base = smb + buf * BUFSZ;
    const int k0 = ch << 5;
    #pragma unroll
    for (int i = 0; i < 2; i++) {
        int idx = tid + 256 * i;
        int r = idx >> 2, q = idx & 3;
        uint32_t sa = base + r * 80 + q * 16;
        size_t g = (size_t)(m0 + r) * 1024 + k0 + q * 8;
        cp16(sa, g_xh + g);
        cp16(sa + A_LO, g_xl + g);
    }
    #pragma unroll
    for (int i = 0; i < 3; i++) {
        int idx = tid + 256 * i;
        int r = idx >> 2, q = idx & 3;
        uint32_t sb = base + B_OFF + r * 80 + q * 16;
        size_t g = (size_t)r * 1024 + k0 + q * 8;
        cp16(sb, g_bh + g);
        cp16(sb + B_LO, g_bl + g);
    }
}

__global__ void __launch_bounds__(256, 1) proj_gemm_kernel()
{
    extern __shared__ __align__(16) char sm[];
    const uint32_t smb = smem_u32(sm);

    const int tid  = threadIdx.x;
    const int wid  = tid >> 5;
    const int lane = tid & 31;
    const int wr   = wid >> 2;
    const int wc   = wid & 3;
    const int m0   = blockIdx.x * 128;

    float c[4][6][4];
    #pragma unroll
    for (int mt = 0; mt < 4; mt++)
        #pragma unroll
        for (int nt = 0; nt < 6; nt++)
            #pragma unroll
            for (int e = 0; e < 4; e++) c[mt][nt][e] = 0.f;

    const uint32_t aoff = (uint32_t)((wr * 64 + (lane & 15)) * 80 + (lane >> 4) * 16);
    const int bg = lane >> 3;
    const uint32_t boff = (uint32_t)((wc * 48 + (lane & 7) + (bg >> 1) * 8) * 80 + (bg & 1) * 16);

    stage_chunk(smb, m0, 0, 0, tid);
    CP_COMMIT();

    for (int ch = 0; ch < 32; ch++) {
        const int buf = ch & 1;
        if (ch < 31) {
            stage_chunk(smb, m0, ch + 1, buf ^ 1, tid);
            CP_COMMIT();
            CP_WAIT(1);
        } else {
            CP_WAIT(0);
        }
        __syncthreads();

        const uint32_t base = smb + buf * BUFSZ;
        #pragma unroll
        for (int k16 = 0; k16 < 2; k16++) {
            uint32_t ah[4][4], al[4][4], bh[3][4], bl[3][4];
            #pragma unroll
            for (int mt = 0; mt < 4; mt++) {
                uint32_t ad = base + aoff + mt * (16 * 80) + k16 * 32;
                ldx4(ah[mt], ad);
                ldx4(al[mt], ad + A_LO);
            }
            #pragma unroll
            for (int np = 0; np < 3; np++) {
                uint32_t bd = base + B_OFF + boff + np * (16 * 80) + k16 * 32;
                ldx4(bh[np], bd);
                ldx4(bl[np], bd + B_LO);
            }
            #pragma unroll
            for (int mt = 0; mt < 4; mt++) {
                #pragma unroll
                for (int nt = 0; nt < 6; nt++) {
                    const int np = nt >> 1, sel = (nt & 1) * 2;
                    mma_bf16(c[mt][nt], ah[mt], bh[np][sel], bh[np][sel + 1]);
                    mma_bf16(c[mt][nt], ah[mt], bl[np][sel], bl[np][sel + 1]);
                    mma_bf16(c[mt][nt], al[mt], bh[np][sel], bh[np][sel + 1]);
                }
            }
        }
        __syncthreads();
    }

    // Epilogue: split to bf16 hi/lo, q scaled by 1/32
    #pragma unroll
    for (int mt = 0; mt < 4; mt++) {
        const int row = m0 + wr * 64 + mt * 16 + (lane >> 2);
        #pragma unroll
        for (int nt = 0; nt < 6; nt++) {
            const int ng  = wc * 48 + nt * 8;
            const int mat = ng >> 6;
            const int col = (ng & 63) + 2 * (lane & 3);
            __nv_bfloat16* dh = (mat == 0) ? g_kh : ((mat == 1) ? g_qh : g_vh);
            __nv_bfloat16* dl = (mat == 0) ? g_kl : ((mat == 1) ? g_ql : g_vl);
            const float s = (mat == 1) ? 0.03125f : 1.0f;
            uint32_t ph, pl;
            split2(c[mt][nt][0] * s, c[mt][nt][1] * s, ph, pl);
            *(uint32_t*)&dh[(size_t)row * 64 + col] = ph;
            *(uint32_t*)&dl[(size_t)row * 64 + col] = pl;
            split2(c[mt][nt][2] * s, c[mt][nt][3] * s, ph, pl);
            *(uint32_t*)&dh[(size_t)(row + 8) * 64 + col] = ph;
            *(uint32_t*)&dl[(size_t)(row + 8) * 64 + col] = pl;
        }
    }
}

// ---------------------------------------------------------------------------
// Tensor-core split-K causal attention.
// grid = (NCH, NQT, B), block = 128 (4 warps x 16 queries).
// smem: Qh @0, Ql @8192, then 2 buffers x {Kh,Kl,Vh,Vl} of 8192 each.
// Layout: row-major 64x64 bf16, 128B rows with XOR-16B swizzle.
// ---------------------------------------------------------------------------
#define SM_KV   16384
#define KVBUF   32768
#define ATTN_SMEM (SM_KV + 2 * KVBUF)

__device__ __forceinline__ void stage_kv(uint32_t base, int b, int s0, int tid)
{
    const size_t g0 = ((size_t)(b * T) + s0) * 64;
    #pragma unroll
    for (int i = 0; i < 4; i++) {
        int idx = tid + 128 * i;
        int row = idx >> 3, q = idx & 7;
        uint32_t dst = base + row * 128 + ((q ^ (row & 7)) << 4);
        size_t src = g0 + row * 64 + q * 8;
        cp16(dst,          g_kh + src);
        cp16(dst +  8192,  g_kl + src);
        cp16(dst + 16384,  g_vh + src);
        cp16(dst + 24576,  g_vl + src);
    }
}

__global__ void __launch_bounds__(128) attn_kernel()
{
    const int chunk = blockIdx.x;
    const int qt    = blockIdx.y;
    const int b     = blockIdx.z;

    const int kbeg = chunk * KCHUNK;
    const int klim = (qt + 1) * QTILE;
    if (kbeg >= klim) return;
    const int ntiles = min(4, (klim - kbeg) >> 6);

    extern __shared__ __align__(16) char sm[];
    const uint32_t smb = smem_u32(sm);
    const int tid  = threadIdx.x;
    const int w    = tid >> 5;
    const int lane = tid & 31;

    // stage Q hi/lo
    {
        const size_t gq = ((size_t)(b * T) + qt * 64) * 64;
        #pragma unroll
        for (int i = 0; i < 4; i++) {
            int idx = tid + 128 * i;
            int row = idx >> 3, q = idx & 7;
            uint32_t dst = smb + row * 128 + ((q ^ (row & 7)) << 4);
            size_t src = gq + row * 64 + q * 8;
            cp16(dst, g_qh + src);
            cp16(dst + 8192, g_ql + src);
        }
    }
    CP_COMMIT();
    stage_kv(smb + SM_KV, b, kbeg, tid);
    CP_COMMIT();

    float o[8][4];
    #pragma unroll
    for (int nt = 0; nt < 8; nt++)
        #pragma unroll
        for (int e = 0; e < 4; e++) o[nt][e] = 0.f;
    float l0 = 0.f, l1 = 0.f;
    uint32_t qh[4][4], ql[4][4];

    for (int kt = 0; kt < ntiles; kt++) {
        CP_WAIT(0);
        __syncthreads();
        if (kt + 1 < ntiles) {
            stage_kv(smb + SM_KV + ((kt + 1) & 1) * KVBUF, b, kbeg + (kt + 1) * 64, tid);
            CP_COMMIT();
        }
        if (kt == 0) {
            #pragma unroll
            for (int ks = 0; ks < 4; ks++) {
                int row = w * 16 + (lane & 15);
                int cg  = ks * 2 + (lane >> 4);
                uint32_t ad = smb + row * 128 + ((cg ^ (row & 7)) << 4);
                ldx4(qh[ks], ad);
                ldx4(ql[ks], ad + 8192);
            }
        }

        const uint32_t base = smb + SM_KV + (kt & 1) * KVBUF;

        // ---- S = Q . K^T (3-term split) ----
        float c[8][4];
        #pragma unroll
        for (int nt = 0; nt < 8; nt++)
            #pragma unroll
            for (int e = 0; e < 4; e++) c[nt][e] = 0.f;

        #pragma unroll
        for (int nb = 0; nb < 4; nb++) {
            #pragma unroll
            for (int ks = 0; ks < 4; ks++) {
                int row = nb * 16 + (lane & 7) + ((lane >> 4) << 3);
                int cg  = ks * 2 + ((lane >> 3) & 1);
                uint32_t ad = base + row * 128 + ((cg ^ (row & 7)) << 4);
                uint32_t bh[4], bl[4];
                ldx4(bh, ad);
                ldx4(bl, ad + 8192);
                mma_bf16(c[2 * nb],     qh[ks], bh[0], bh[1]);
                mma_bf16(c[2 * nb],     qh[ks], bl[0], bl[1]);
                mma_bf16(c[2 * nb],     ql[ks], bh[0], bh[1]);
                mma_bf16(c[2 * nb + 1], qh[ks], bh[2], bh[3]);
                mma_bf16(c[2 * nb + 1], qh[ks], bl[2], bl[3]);
                mma_bf16(c[2 * nb + 1], ql[ks], bh[2], bh[3]);
            }
        }

        // ---- exp + mask + row sums ----
        const bool diag = (kbeg + kt * 64) == qt * 64;
        const int trow = w * 16 + (lane >> 2);
        #pragma unroll
        for (int nt = 0; nt < 8; nt++) {
            const int s0l = nt * 8 + ((lane & 3) << 1);
            float p0, p1, p2, p3;
            if (diag) {
                p0 = (s0l     <= trow)     ? __expf(c[nt][0]) : 0.f;
                p1 = (s0l + 1 <= trow)     ? __expf(c[nt][1]) : 0.f;
                p2 = (s0l     <= trow + 8) ? __expf(c[nt][2]) : 0.f;
                p3 = (s0l + 1 <= trow + 8) ? __expf(c[nt][3]) : 0.f;
            } else {
                p0 = __expf(c[nt][0]);
                p1 = __expf(c[nt][1]);
                p2 = __expf(c[nt][2]);
                p3 = __expf(c[nt][3]);
            }
            l0 += p0 + p1;
            l1 += p2 + p3;
            c[nt][0] = p0; c[nt][1] = p1; c[nt][2] = p2; c[nt][3] = p3;
        }

        // ---- O += P . V (3-term split; P fragments re-packed in registers) ----
        #pragma unroll
        for (int ks = 0; ks < 4; ks++) {
            uint32_t pah[4], pal[4];
            split2(c[2 * ks][0],     c[2 * ks][1],     pah[0], pal[0]);
            split2(c[2 * ks][2],     c[2 * ks][3],     pah[1], pal[1]);
            split2(c[2 * ks + 1][0], c[2 * ks + 1][1], pah[2], pal[2]);
            split2(c[2 * ks + 1][2], c[2 * ks + 1][3], pah[3], pal[3]);
            #pragma unroll
            for (int hb = 0; hb < 4; hb++) {
                int vrow = ks * 16 + (lane & 15);
                int cg   = hb * 2 + (lane >> 4);
                uint32_t va = base + 16384 + vrow * 128 + ((cg ^ (vrow & 7)) << 4);
                uint32_t vh[4], vl[4];
                ldx4t(vh, va);
                ldx4t(vl, va + 8192);
                mma_bf16(o[2 * hb],     pah, vh[0], vh[1]);
                mma_bf16(o[2 * hb],     pah, vl[0], vl[1]);
                mma_bf16(o[2 * hb],     pal, vh[0], vh[1]);
                mma_bf16(o[2 * hb + 1], pah, vh[2], vh[3]);
                mma_bf16(o[2 * hb + 1], pah, vl[2], vl[3]);
                mma_bf16(o[2 * hb + 1], pal, vh[2], vh[3]);
            }
        }
    }

    // ---- reduce l across the quad owning each row, write partials ----
    l0 += __shfl_xor_sync(0xffffffffu, l0, 1);
    l0 += __shfl_xor_sync(0xffffffffu, l0, 2);
    l1 += __shfl_xor_sync(0xffffffffu, l1, 1);
    l1 += __shfl_xor_sync(0xffffffffu, l1, 2);

    const size_t pq = (((size_t)(b * NQT + qt)) * NCH + chunk) * 64;
    const int row = w * 16 + (lane >> 2);
    #pragma unroll
    for (int nt = 0; nt < 8; nt++) {
        const int col = nt * 8 + ((lane & 3) << 1);
        float2 w0; w0.x = o[nt][0]; w0.y = o[nt][1];
        float2 w1; w1.x = o[nt][2]; w1.y = o[nt][3];
        *(float2*)&g_pacc[(pq + row) * 64 + col]     = w0;
        *(float2*)&g_pacc[(pq + row + 8) * 64 + col] = w1;
    }
    if ((lane & 3) == 0) {
        g_pl[pq + row]     = l0;
        g_pl[pq + row + 8] = l1;
    }
}

// ---------------------------------------------------------------------------
// combine split-K partials
// ---------------------------------------------------------------------------
__global__ void __launch_bounds__(256) combine_kernel(float* __restrict__ out)
{
    const int b  = blockIdx.y;
    const int th = blockIdx.x * 256 + threadIdx.x;
    const int t  = th >> 6;
    const int h  = th & 63;
    const int qt = t >> 6;
    const int qi = t & 63;
    const int nch = (t >> 8) + 1;

    const size_t base = ((size_t)(b * NQT + qt)) * NCH;
    float a = 0.f, L = 0.f;
    for (int c = 0; c < nch; c++) {
        a += g_pacc[((base + c) * QTILE + qi) * H + h];
        L += g_pl[(base + c) * QTILE + qi];
    }
    out[((size_t)(b * T + t)) * H + h] = a / L;
}

extern "C" void kernel_launch(void* const* d_in, const int* in_sizes, int n_in,
                              void* d_out, int out_size)
{
    const float* x  = (const float*)d_in[0];
    const float* Wk = (const float*)d_in[1];
    const float* Wq = (const float*)d_in[2];
    const float* Wv = (const float*)d_in[3];

    cudaFuncSetAttribute(proj_gemm_kernel,
                         cudaFuncAttributeMaxDynamicSharedMemorySize, 2 * BUFSZ);
    cudaFuncSetAttribute(attn_kernel,
                         cudaFuncAttributeMaxDynamicSharedMemorySize, ATTN_SMEM);

    convx_kernel<<<16384, 256>>>(x);
    convw_kernel<<<768, 256>>>(Wk, Wq, Wv);
    proj_gemm_kernel<<<128, 256, 2 * BUFSZ>>>();
    attn_kernel<<<dim3(NCH, NQT, B), 128, ATTN_SMEM>>>();
    combine_kernel<<<dim3(T * H / 256, B), 256>>>((float*)d_out);
}

// round 6
// speedup vs baseline: 6.7892x; 1.1912x over previous
#include <cuda_runtime.h>
#include <cuda_bf16.h>
#include <cstdint>

#define B 8
#define T 2048
#define C 1024
#define H 64
#define QTILE 64
#define NQT   (T / QTILE)
#define KCHUNK 256
#define NCH    8

typedef unsigned long long ull;

// ---------------- scratch (__device__ globals; no allocation allowed) -------
__device__ float g_pacc[B * NQT * NCH * QTILE * H];
__device__ float g_pl[B * NQT * NCH * QTILE];
__device__ __nv_bfloat16 g_bh[3 * H * C];   // W^T hi: [192 n][1024 k]
__device__ __nv_bfloat16 g_bl[3 * H * C];   // W^T lo
// projected q/k/v as bf16 hi/lo (q pre-scaled by 1/32)
__device__ __nv_bfloat16 g_qh[B * T * H];
__device__ __nv_bfloat16 g_ql[B * T * H];
__device__ __nv_bfloat16 g_kh[B * T * H];
__device__ __nv_bfloat16 g_kl[B * T * H];
__device__ __nv_bfloat16 g_vh[B * T * H];
__device__ __nv_bfloat16 g_vl[B * T * H];

// ---------------- helpers ----------------------------------------------------
__device__ __forceinline__ uint32_t smem_u32(const void* p) {
    uint32_t a;
    asm("{ .reg .u64 t; cvta.to.shared.u64 t, %1; cvt.u32.u64 %0, t; }"
        : "=r"(a) : "l"(p));
    return a;
}
__device__ __forceinline__ void cp16(uint32_t saddr, const void* gptr) {
    asm volatile("cp.async.cg.shared.global [%0], [%1], 16;"
                 :: "r"(saddr), "l"(__cvta_generic_to_global(gptr)) : "memory");
}
#define CP_COMMIT() asm volatile("cp.async.commit_group;" ::: "memory")
#define CP_WAIT(n)  asm volatile("cp.async.wait_group %0;" :: "n"(n) : "memory")

__device__ __forceinline__ void ldx4(uint32_t* r, uint32_t addr) {
    asm volatile("ldmatrix.sync.aligned.m8n8.x4.shared.b16 {%0,%1,%2,%3}, [%4];"
                 : "=r"(r[0]), "=r"(r[1]), "=r"(r[2]), "=r"(r[3]) : "r"(addr));
}
__device__ __forceinline__ void ldx4t(uint32_t* r, uint32_t addr) {
    asm volatile("ldmatrix.sync.aligned.m8n8.x4.trans.shared.b16 {%0,%1,%2,%3}, [%4];"
                 : "=r"(r[0]), "=r"(r[1]), "=r"(r[2]), "=r"(r[3]) : "r"(addr));
}
__device__ __forceinline__ void mma_bf16(float* c, const uint32_t* a,
                                         uint32_t b0, uint32_t b1) {
    asm volatile(
        "mma.sync.aligned.m16n8k16.row.col.f32.bf16.bf16.f32 "
        "{%0,%1,%2,%3}, {%4,%5,%6,%7}, {%8,%9}, {%0,%1,%2,%3};"
        : "+f"(c[0]), "+f"(c[1]), "+f"(c[2]), "+f"(c[3])
        : "r"(a[0]), "r"(a[1]), "r"(a[2]), "r"(a[3]), "r"(b0), "r"(b1));
}
__device__ __forceinline__ uint32_t packbf(float lo, float hi) {
    uint32_t r;
    asm("cvt.rn.bf16x2.f32 %0, %1, %2;" : "=r"(r) : "f"(hi), "f"(lo));
    return r;
}
__device__ __forceinline__ void split2(float f0, float f1, uint32_t& ph, uint32_t& pl) {
    ph = packbf(f0, f1);
    float h0 = __bfloat162float(__ushort_as_bfloat16((unsigned short)(ph & 0xffff)));
    float h1 = __bfloat162float(__ushort_as_bfloat16((unsigned short)(ph >> 16)));
    pl = packbf(f0 - h0, f1 - h1);
}
__device__ __forceinline__ void sts8(uint32_t addr, uint32_t a, uint32_t b) {
    asm volatile("st.shared.v2.b32 [%0], {%1,%2};" :: "r"(addr), "r"(a), "r"(b) : "memory");
}

// ---------------------------------------------------------------------------
// W -> transposed bf16 hi/lo
// ---------------------------------------------------------------------------
__global__ void __launch_bounds__(256) convw_kernel(
    const float* __restrict__ Wk, const float* __restrict__ Wq,
    const float* __restrict__ Wv)
{
    const int idx = blockIdx.x * 256 + threadIdx.x;
    const int o = idx >> 16;
    const int n = (idx >> 10) & 63;
    const int k = idx & 1023;
    const float* W = (o == 0) ? Wk : ((o == 1) ? Wq : Wv);
    float w = W[k * 64 + n];
    __nv_bfloat16 h = __float2bfloat16_rn(w);
    __nv_bfloat16 l = __float2bfloat16_rn(w - __bfloat162float(h));
    g_bh[idx] = h;
    g_bl[idx] = l;
}

// ---------------------------------------------------------------------------
// Projection GEMM (HMMA, split-bf16), x converted in-kernel (fp32 LDG ->
// register hi/lo split -> STS). Block tile 64x192, warp tile 32x48,
// k chunk 32, register+smem double-buffered pipeline.
// smem per buffer (40960 B): Ah @0 (64*80), Al @5120, Bh @10240 (192*80), Bl @25600
// ---------------------------------------------------------------------------
#define BUFSZ 40960
#define A_LO  5120
#define B_OFF 10240
#define B_LO  15360

__device__ __forceinline__ void ldg_a(const float* __restrict__ x, int m0,
                                      int ch, int tid, float4* r)
{
    const int k0 = ch << 5;
    #pragma unroll
    for (int i = 0; i < 2; i++) {
        int idx = tid + 256 * i;        // 0..511
        int row = idx >> 3, q = idx & 7;
        r[i] = *(const float4*)&x[(size_t)(m0 + row) * 1024 + k0 + q * 4];
    }
}
__device__ __forceinline__ void sts_a(uint32_t base, int tid, const float4* r)
{
    #pragma unroll
    for (int i = 0; i < 2; i++) {
        int idx = tid + 256 * i;
        int row = idx >> 3, q = idx & 7;
        uint32_t ph01, pl01, ph23, pl23;
        split2(r[i].x, r[i].y, ph01, pl01);
        split2(r[i].z, r[i].w, ph23, pl23);
        uint32_t d = base + row * 80 + q * 8;
        sts8(d, ph01, ph23);
        sts8(d + A_LO, pl01, pl23);
    }
}
__device__ __forceinline__ void stage_b(uint32_t base, int ch, int tid)
{
    const int k0 = ch << 5;
    #pragma unroll
    for (int i = 0; i < 3; i++) {
        int idx = tid + 256 * i;        // 0..767
        int r = idx >> 2, q = idx & 3;
        uint32_t sb = base + B_OFF + r * 80 + q * 16;
        size_t g = (size_t)r * 1024 + k0 + q * 8;
        cp16(sb, g_bh + g);
        cp16(sb + B_LO, g_bl + g);
    }
}

__global__ void __launch_bounds__(256, 2) proj_gemm_kernel(const float* __restrict__ x)
{
    extern __shared__ __align__(16) char sm[];
    const uint32_t smb = smem_u32(sm);

    const int tid  = threadIdx.x;
    const int wid  = tid >> 5;
    const int lane = tid & 31;
    const int wr   = wid >> 2;          // 0..1 (32 rows each)
    const int wc   = wid & 3;           // 0..3 (48 cols each)
    const int m0   = blockIdx.x * 64;

    float c[2][6][4];
    #pragma unroll
    for (int mt = 0; mt < 2; mt++)
        #pragma unroll
        for (int nt = 0; nt < 6; nt++)
            #pragma unroll
            for (int e = 0; e < 4; e++) c[mt][nt][e] = 0.f;

    const uint32_t aoff = (uint32_t)((wr * 32 + (lane & 15)) * 80 + (lane >> 4) * 16);
    const int bg = lane >> 3;
    const uint32_t boff = (uint32_t)((wc * 48 + (lane & 7) + (bg >> 1) * 8) * 80 + (bg & 1) * 16);

    float4 areg[2];
    // prologue: A0 -> buf0; B0, then A1 into regs, B1 in flight
    ldg_a(x, m0, 0, tid, areg);
    sts_a(smb, tid, areg);
    stage_b(smb, 0, tid);
    CP_COMMIT();
    ldg_a(x, m0, 1, tid, areg);
    stage_b(smb + BUFSZ, 1, tid);
    CP_COMMIT();

    for (int ch = 0; ch < 32; ch++) {
        if (ch < 31) { CP_WAIT(1); } else { CP_WAIT(0); }
        __syncthreads();

        const uint32_t base = smb + (ch & 1) * BUFSZ;
        #pragma unroll
        for (int k16 = 0; k16 < 2; k16++) {
            uint32_t ah[2][4], al[2][4], bh[3][4], bl[3][4];
            #pragma unroll
            for (int mt = 0; mt < 2; mt++) {
                uint32_t ad = base + aoff + mt * (16 * 80) + k16 * 32;
                ldx4(ah[mt], ad);
                ldx4(al[mt], ad + A_LO);
            }
            #pragma unroll
            for (int np = 0; np < 3; np++) {
                uint32_t bd = base + B_OFF + boff + np * (16 * 80) + k16 * 32;
                ldx4(bh[np], bd);
                ldx4(bl[np], bd + B_LO);
            }
            #pragma unroll
            for (int mt = 0; mt < 2; mt++) {
                #pragma unroll
                for (int nt = 0; nt < 6; nt++) {
                    const int np = nt >> 1, sel = (nt & 1) * 2;
                    mma_bf16(c[mt][nt], ah[mt], bh[np][sel], bh[np][sel + 1]);
                    mma_bf16(c[mt][nt], ah[mt], bl[np][sel], bl[np][sel + 1]);
                    mma_bf16(c[mt][nt], al[mt], bh[np][sel], bh[np][sel + 1]);
                }
            }
        }

        if (ch + 1 < 32) {
            __syncthreads();   // everyone done reading buf(ch) before cp into it
            sts_a(smb + ((ch + 1) & 1) * BUFSZ, tid, areg);
            if (ch + 2 < 32) {
                ldg_a(x, m0, ch + 2, tid, areg);
                stage_b(smb + ((ch + 2) & 1) * BUFSZ, ch + 2, tid);
                CP_COMMIT();
            }
        }
    }

    // Epilogue: split to bf16 hi/lo, q scaled by 1/32
    #pragma unroll
    for (int mt = 0; mt < 2; mt++) {
        const int row = m0 + wr * 32 + mt * 16 + (lane >> 2);
        #pragma unroll
        for (int nt = 0; nt < 6; nt++) {
            const int ng  = wc * 48 + nt * 8;
            const int mat = ng >> 6;
            const int col = (ng & 63) + 2 * (lane & 3);
            __nv_bfloat16* dh = (mat == 0) ? g_kh : ((mat == 1) ? g_qh : g_vh);
            __nv_bfloat16* dl = (mat == 0) ? g_kl : ((mat == 1) ? g_ql : g_vl);
            const float s = (mat == 1) ? 0.03125f : 1.0f;
            uint32_t ph, pl;
            split2(c[mt][nt][0] * s, c[mt][nt][1] * s, ph, pl);
            *(uint32_t*)&dh[(size_t)row * 64 + col] = ph;
            *(uint32_t*)&dl[(size_t)row * 64 + col] = pl;
            split2(c[mt][nt][2] * s, c[mt][nt][3] * s, ph, pl);
            *(uint32_t*)&dh[(size_t)(row + 8) * 64 + col] = ph;
            *(uint32_t*)&dl[(size_t)(row + 8) * 64 + col] = pl;
        }
    }
}

// ---------------------------------------------------------------------------
// Tensor-core split-K causal attention.
// grid = (NCH, NQT, B), block = 128 (4 warps x 16 queries).
// smem 64KB: buf0 @0 (Kh,Kl,Vh,Vl x 8KB), buf1 @32KB; Q hi/lo overlays the
// first 16KB of buf1 (consumed into registers before buf1's first write).
// ---------------------------------------------------------------------------
#define KVBUF   32768
#define ATTN_SMEM 65536

__device__ __forceinline__ void stage_kv(uint32_t base, int b, int s0, int tid)
{
    const size_t g0 = ((size_t)(b * T) + s0) * 64;
    #pragma unroll
    for (int i = 0; i < 4; i++) {
        int idx = tid + 128 * i;
        int row = idx >> 3, q = idx & 7;
        uint32_t dst = base + row * 128 + ((q ^ (row & 7)) << 4);
        size_t src = g0 + row * 64 + q * 8;
        cp16(dst,          g_kh + src);
        cp16(dst +  8192,  g_kl + src);
        cp16(dst + 16384,  g_vh + src);
        cp16(dst + 24576,  g_vl + src);
    }
}

__global__ void __launch_bounds__(128) attn_kernel()
{
    const int chunk = blockIdx.x;
    const int qt    = blockIdx.y;
    const int b     = blockIdx.z;

    const int kbeg = chunk * KCHUNK;
    const int klim = (qt + 1) * QTILE;
    if (kbeg >= klim) return;
    const int ntiles = min(4, (klim - kbeg) >> 6);

    extern __shared__ __align__(16) char sm[];
    const uint32_t smb = smem_u32(sm);
    const int tid  = threadIdx.x;
    const int w    = tid >> 5;
    const int lane = tid & 31;

    // stage Q hi/lo into the buf1-overlay region, and KV tile 0 into buf0
    {
        const size_t gq = ((size_t)(b * T) + qt * 64) * 64;
        #pragma unroll
        for (int i = 0; i < 4; i++) {
            int idx = tid + 128 * i;
            int row = idx >> 3, q = idx & 7;
            uint32_t dst = smb + KVBUF + row * 128 + ((q ^ (row & 7)) << 4);
            size_t src = gq + row * 64 + q * 8;
            cp16(dst, g_qh + src);
            cp16(dst + 8192, g_ql + src);
        }
    }
    stage_kv(smb, b, kbeg, tid);
    CP_COMMIT();
    CP_WAIT(0);
    __syncthreads();

    // Q fragments -> registers (frees the overlay region)
    uint32_t qh[4][4], ql[4][4];
    #pragma unroll
    for (int ks = 0; ks < 4; ks++) {
        int row = w * 16 + (lane & 15);
        int cg  = ks * 2 + (lane >> 4);
        uint32_t ad = smb + KVBUF + row * 128 + ((cg ^ (row & 7)) << 4);
        ldx4(qh[ks], ad);
        ldx4(ql[ks], ad + 8192);
    }

    float o[8][4];
    #pragma unroll
    for (int nt = 0; nt < 8; nt++)
        #pragma unroll
        for (int e = 0; e < 4; e++) o[nt][e] = 0.f;
    float l0 = 0.f, l1 = 0.f;

    for (int kt = 0; kt < ntiles; kt++) {
        __syncthreads();   // kt=0: Q frag reads done; kt>0: buf((kt+1)&1) readers done
        if (kt + 1 < ntiles) {
            stage_kv(smb + ((kt + 1) & 1) * KVBUF, b, kbeg + (kt + 1) * 64, tid);
            CP_COMMIT();
            CP_WAIT(1);
        } else {
            CP_WAIT(0);
        }
        __syncthreads();

        const uint32_t base = smb + (kt & 1) * KVBUF;

        // ---- S = Q . K^T (3-term split) ----
        float c[8][4];
        #pragma unroll
        for (int nt = 0; nt < 8; nt++)
            #pragma unroll
            for (int e = 0; e < 4; e++) c[nt][e] = 0.f;

        #pragma unroll
        for (int nb = 0; nb < 4; nb++) {
            #pragma unroll
            for (int ks = 0; ks < 4; ks++) {
                int row = nb * 16 + (lane & 7) + ((lane >> 4) << 3);
                int cg  = ks * 2 + ((lane >> 3) & 1);
                uint32_t ad = base + row * 128 + ((cg ^ (row & 7)) << 4);
                uint32_t bh[4], bl[4];
                ldx4(bh, ad);
                ldx4(bl, ad + 8192);
                mma_bf16(c[2 * nb],     qh[ks], bh[0], bh[1]);
                mma_bf16(c[2 * nb],     qh[ks], bl[0], bl[1]);
                mma_bf16(c[2 * nb],     ql[ks], bh[0], bh[1]);
                mma_bf16(c[2 * nb + 1], qh[ks], bh[2], bh[3]);
                mma_bf16(c[2 * nb + 1], qh[ks], bl[2], bl[3]);
                mma_bf16(c[2 * nb + 1], ql[ks], bh[2], bh[3]);
            }
        }

        // ---- exp + mask + row sums ----
        const bool diag = (kbeg + kt * 64) == qt * 64;
        const int trow = w * 16 + (lane >> 2);
        #pragma unroll
        for (int nt = 0; nt < 8; nt++) {
            const int s0l = nt * 8 + ((lane & 3) << 1);
            float p0, p1, p2, p3;
            if (diag) {
                p0 = (s0l     <= trow)     ? __expf(c[nt][0]) : 0.f;
                p1 = (s0l + 1 <= trow)     ? __expf(c[nt][1]) : 0.f;
                p2 = (s0l     <= trow + 8) ? __expf(c[nt][2]) : 0.f;
                p3 = (s0l + 1 <= trow + 8) ? __expf(c[nt][3]) : 0.f;
            } else {
                p0 = __expf(c[nt][0]);
                p1 = __expf(c[nt][1]);
                p2 = __expf(c[nt][2]);
                p3 = __expf(c[nt][3]);
            }
            l0 += p0 + p1;
            l1 += p2 + p3;
            c[nt][0] = p0; c[nt][1] = p1; c[nt][2] = p2; c[nt][3] = p3;
        }

        // ---- O += P . V (3-term split; P re-packed in registers) ----
        #pragma unroll
        for (int ks = 0; ks < 4; ks++) {
            uint32_t pah[4], pal[4];
            split2(c[2 * ks][0],     c[2 * ks][1],     pah[0], pal[0]);
            split2(c[2 * ks][2],     c[2 * ks][3],     pah[1], pal[1]);
            split2(c[2 * ks + 1][0], c[2 * ks + 1][1], pah[2], pal[2]);
            split2(c[2 * ks + 1][2], c[2 * ks + 1][3], pah[3], pal[3]);
            #pragma unroll
            for (int hb = 0; hb < 4; hb++) {
                int vrow = ks * 16 + (lane & 15);
                int cg   = hb * 2 + (lane >> 4);
                uint32_t va = base + 16384 + vrow * 128 + ((cg ^ (vrow & 7)) << 4);
                uint32_t vh[4], vl[4];
                ldx4t(vh, va);
                ldx4t(vl, va + 8192);
                mma_bf16(o[2 * hb],     pah, vh[0], vh[1]);
                mma_bf16(o[2 * hb],     pah, vl[0], vl[1]);
                mma_bf16(o[2 * hb],     pal, vh[0], vh[1]);
                mma_bf16(o[2 * hb + 1], pah, vh[2], vh[3]);
                mma_bf16(o[2 * hb + 1], pah, vl[2], vl[3]);
                mma_bf16(o[2 * hb + 1], pal, vh[2], vh[3]);
            }
        }
    }

    // ---- reduce l across quads, write partials ----
    l0 += __shfl_xor_sync(0xffffffffu, l0, 1);
    l0 += __shfl_xor_sync(0xffffffffu, l0, 2);
    l1 += __shfl_xor_sync(0xffffffffu, l1, 1);
    l1 += __shfl_xor_sync(0xffffffffu, l1, 2);

    const size_t pq = (((size_t)(b * NQT + qt)) * NCH + chunk) * 64;
    const int row = w * 16 + (lane >> 2);
    #pragma unroll
    for (int nt = 0; nt < 8; nt++) {
        const int col = nt * 8 + ((lane & 3) << 1);
        float2 w0; w0.x = o[nt][0]; w0.y = o[nt][1];
        float2 w1; w1.x = o[nt][2]; w1.y = o[nt][3];
        *(float2*)&g_pacc[(pq + row) * 64 + col]     = w0;
        *(float2*)&g_pacc[(pq + row + 8) * 64 + col] = w1;
    }
    if ((lane & 3) == 0) {
        g_pl[pq + row]     = l0;
        g_pl[pq + row + 8] = l1;
    }
}

// ---------------------------------------------------------------------------
// combine split-K partials
// ---------------------------------------------------------------------------
__global__ void __launch_bounds__(256) combine_kernel(float* __restrict__ out)
{
    const int b  = blockIdx.y;
    const int th = blockIdx.x * 256 + threadIdx.x;
    const int t  = th >> 6;
    const int h  = th & 63;
    const int qt = t >> 6;
    const int qi = t & 63;
    const int nch = (t >> 8) + 1;

    const size_t base = ((size_t)(b * NQT + qt)) * NCH;
    float a = 0.f, L = 0.f;
    for (int c = 0; c < nch; c++) {
        a += g_pacc[((base + c) * QTILE + qi) * H + h];
        L += g_pl[(base + c) * QTILE + qi];
    }
    out[((size_t)(b * T + t)) * H + h] = a / L;
}

extern "C" void kernel_launch(void* const* d_in, const int* in_sizes, int n_in,
                              void* d_out, int out_size)
{
    const float* x  = (const float*)d_in[0];
    const float* Wk = (const float*)d_in[1];
    const float* Wq = (const float*)d_in[2];
    const float* Wv = (const float*)d_in[3];

    cudaFuncSetAttribute(proj_gemm_kernel,
                         cudaFuncAttributeMaxDynamicSharedMemorySize, 2 * BUFSZ);
    cudaFuncSetAttribute(attn_kernel,
                         cudaFuncAttributeMaxDynamicSharedMemorySize, ATTN_SMEM);

    convw_kernel<<<768, 256>>>(Wk, Wq, Wv);
    proj_gemm_kernel<<<256, 256, 2 * BUFSZ>>>(x);
    attn_kernel<<<dim3(NCH, NQT, B), 128, ATTN_SMEM>>>();
    combine_kernel<<<dim3(T * H / 256, B), 256>>>((float*)d_out);
}

// round 7
// speedup vs baseline: 8.2700x; 1.2181x over previous
#include <cuda_runtime.h>
#include <cuda_bf16.h>
#include <cuda_fp16.h>
#include <cstdint>

#define B 8
#define T 2048
#define C 1024
#define H 64
#define QTILE 64
#define NQT   (T / QTILE)
#define KCHUNK 256
#define NCH    8

// ---------------- scratch (__device__ globals; no allocation allowed) -------
__device__ float g_pacc[B * NQT * NCH * QTILE * H];
__device__ float g_pl[B * NQT * NCH * QTILE];
__device__ __nv_bfloat16 g_bh[3 * H * C];   // W^T hi: [192 n][1024 k]
__device__ __nv_bfloat16 g_bl[3 * H * C];   // W^T lo
// projected q/k/v as fp16 (q pre-scaled by 1/32)
__device__ __half g_qh[B * T * H];
__device__ __half g_kh[B * T * H];
__device__ __half g_vh[B * T * H];

// ---------------- helpers ----------------------------------------------------
__device__ __forceinline__ uint32_t smem_u32(const void* p) {
    uint32_t a;
    asm("{ .reg .u64 t; cvta.to.shared.u64 t, %1; cvt.u32.u64 %0, t; }"
        : "=r"(a) : "l"(p));
    return a;
}
__device__ __forceinline__ void cp16(uint32_t saddr, const void* gptr) {
    asm volatile("cp.async.cg.shared.global [%0], [%1], 16;"
                 :: "r"(saddr), "l"(__cvta_generic_to_global(gptr)) : "memory");
}
#define CP_COMMIT() asm volatile("cp.async.commit_group;" ::: "memory")
#define CP_WAIT(n)  asm volatile("cp.async.wait_group %0;" :: "n"(n) : "memory")

__device__ __forceinline__ void ldx4(uint32_t* r, uint32_t addr) {
    asm volatile("ldmatrix.sync.aligned.m8n8.x4.shared.b16 {%0,%1,%2,%3}, [%4];"
                 : "=r"(r[0]), "=r"(r[1]), "=r"(r[2]), "=r"(r[3]) : "r"(addr));
}
__device__ __forceinline__ void ldx4t(uint32_t* r, uint32_t addr) {
    asm volatile("ldmatrix.sync.aligned.m8n8.x4.trans.shared.b16 {%0,%1,%2,%3}, [%4];"
                 : "=r"(r[0]), "=r"(r[1]), "=r"(r[2]), "=r"(r[3]) : "r"(addr));
}
__device__ __forceinline__ void mma_bf16(float* c, const uint32_t* a,
                                         uint32_t b0, uint32_t b1) {
    asm volatile(
        "mma.sync.aligned.m16n8k16.row.col.f32.bf16.bf16.f32 "
        "{%0,%1,%2,%3}, {%4,%5,%6,%7}, {%8,%9}, {%0,%1,%2,%3};"
        : "+f"(c[0]), "+f"(c[1]), "+f"(c[2]), "+f"(c[3])
        : "r"(a[0]), "r"(a[1]), "r"(a[2]), "r"(a[3]), "r"(b0), "r"(b1));
}
__device__ __forceinline__ void mma_f16(float* c, const uint32_t* a,
                                        uint32_t b0, uint32_t b1) {
    asm volatile(
        "mma.sync.aligned.m16n8k16.row.col.f32.f16.f16.f32 "
        "{%0,%1,%2,%3}, {%4,%5,%6,%7}, {%8,%9}, {%0,%1,%2,%3};"
        : "+f"(c[0]), "+f"(c[1]), "+f"(c[2]), "+f"(c[3])
        : "r"(a[0]), "r"(a[1]), "r"(a[2]), "r"(a[3]), "r"(b0), "r"(b1));
}
__device__ __forceinline__ uint32_t packbf(float lo, float hi) {
    uint32_t r;
    asm("cvt.rn.bf16x2.f32 %0, %1, %2;" : "=r"(r) : "f"(hi), "f"(lo));
    return r;
}
__device__ __forceinline__ uint32_t packh(float lo, float hi) {
    uint32_t r;
    asm("cvt.rn.f16x2.f32 %0, %1, %2;" : "=r"(r) : "f"(hi), "f"(lo));
    return r;
}
__device__ __forceinline__ void split2(float f0, float f1, uint32_t& ph, uint32_t& pl) {
    ph = packbf(f0, f1);
    float h0 = __bfloat162float(__ushort_as_bfloat16((unsigned short)(ph & 0xffff)));
    float h1 = __bfloat162float(__ushort_as_bfloat16((unsigned short)(ph >> 16)));
    pl = packbf(f0 - h0, f1 - h1);
}
__device__ __forceinline__ void sts8(uint32_t addr, uint32_t a, uint32_t b) {
    asm volatile("st.shared.v2.b32 [%0], {%1,%2};" :: "r"(addr), "r"(a), "r"(b) : "memory");
}

// ---------------------------------------------------------------------------
// W -> transposed bf16 hi/lo
// ---------------------------------------------------------------------------
__global__ void __launch_bounds__(256) convw_kernel(
    const float* __restrict__ Wk, const float* __restrict__ Wq,
    const float* __restrict__ Wv)
{
    const int idx = blockIdx.x * 256 + threadIdx.x;
    const int o = idx >> 16;
    const int n = (idx >> 10) & 63;
    const int k = idx & 1023;
    const float* W = (o == 0) ? Wk : ((o == 1) ? Wq : Wv);
    float w = W[k * 64 + n];
    __nv_bfloat16 h = __float2bfloat16_rn(w);
    __nv_bfloat16 l = __float2bfloat16_rn(w - __bfloat162float(h));
    g_bh[idx] = h;
    g_bl[idx] = l;
}

// ---------------------------------------------------------------------------
// Projection GEMM (HMMA, split-bf16 3-term), x converted in-kernel.
// Block tile 64x192, warp tile 32x48, k chunk 32, double-buffered.
// Pipeline order: wait B(ch) -> sync -> STS A(ch+1) -> compute(ch)
//                 -> LDG A(ch+2) -> sync -> cp.async B(ch+2).
// smem per buffer (40960 B): Ah @0, Al @5120, Bh @10240, Bl @25600
// ---------------------------------------------------------------------------
#define BUFSZ 40960
#define A_LO  5120
#define B_OFF 10240
#define B_LO  15360

__device__ __forceinline__ void ldg_a(const float* __restrict__ x, int m0,
                                      int ch, int tid, float4* r)
{
    const int k0 = ch << 5;
    #pragma unroll
    for (int i = 0; i < 2; i++) {
        int idx = tid + 256 * i;
        int row = idx >> 3, q = idx & 7;
        r[i] = *(const float4*)&x[(size_t)(m0 + row) * 1024 + k0 + q * 4];
    }
}
__device__ __forceinline__ void sts_a(uint32_t base, int tid, const float4* r)
{
    #pragma unroll
    for (int i = 0; i < 2; i++) {
        int idx = tid + 256 * i;
        int row = idx >> 3, q = idx & 7;
        uint32_t ph01, pl01, ph23, pl23;
        split2(r[i].x, r[i].y, ph01, pl01);
        split2(r[i].z, r[i].w, ph23, pl23);
        uint32_t d = base + row * 80 + q * 8;
        sts8(d, ph01, ph23);
        sts8(d + A_LO, pl01, pl23);
    }
}
__device__ __forceinline__ void stage_b(uint32_t base, int ch, int tid)
{
    const int k0 = ch << 5;
    #pragma unroll
    for (int i = 0; i < 3; i++) {
        int idx = tid + 256 * i;
        int r = idx >> 2, q = idx & 3;
        uint32_t sb = base + B_OFF + r * 80 + q * 16;
        size_t g = (size_t)r * 1024 + k0 + q * 8;
        cp16(sb, g_bh + g);
        cp16(sb + B_LO, g_bl + g);
    }
}

__global__ void __launch_bounds__(256, 2) proj_gemm_kernel(const float* __restrict__ x)
{
    extern __shared__ __align__(16) char sm[];
    const uint32_t smb = smem_u32(sm);

    const int tid  = threadIdx.x;
    const int wid  = tid >> 5;
    const int lane = tid & 31;
    const int wr   = wid >> 2;
    const int wc   = wid & 3;
    const int m0   = blockIdx.x * 64;

    float c[2][6][4];
    #pragma unroll
    for (int mt = 0; mt < 2; mt++)
        #pragma unroll
        for (int nt = 0; nt < 6; nt++)
            #pragma unroll
            for (int e = 0; e < 4; e++) c[mt][nt][e] = 0.f;

    const uint32_t aoff = (uint32_t)((wr * 32 + (lane & 15)) * 80 + (lane >> 4) * 16);
    const int bg = lane >> 3;
    const uint32_t boff = (uint32_t)((wc * 48 + (lane & 7) + (bg >> 1) * 8) * 80 + (bg & 1) * 16);

    float4 areg[2];
    ldg_a(x, m0, 0, tid, areg);
    sts_a(smb, tid, areg);
    stage_b(smb, 0, tid);
    CP_COMMIT();
    ldg_a(x, m0, 1, tid, areg);
    stage_b(smb + BUFSZ, 1, tid);
    CP_COMMIT();

    for (int ch = 0; ch < 32; ch++) {
        if (ch < 31) { CP_WAIT(1); } else { CP_WAIT(0); }
        __syncthreads();

        // STS A(ch+1) into the opposite buffer (disjoint from compute reads)
        if (ch + 1 < 32)
            sts_a(smb + ((ch + 1) & 1) * BUFSZ, tid, areg);

        const uint32_t base = smb + (ch & 1) * BUFSZ;
        #pragma unroll
        for (int k16 = 0; k16 < 2; k16++) {
            uint32_t ah[2][4], al[2][4], bh[3][4], bl[3][4];
            #pragma unroll
            for (int mt = 0; mt < 2; mt++) {
                uint32_t ad = base + aoff + mt * (16 * 80) + k16 * 32;
                ldx4(ah[mt], ad);
                ldx4(al[mt], ad + A_LO);
            }
            #pragma unroll
            for (int np = 0; np < 3; np++) {
                uint32_t bd = base + B_OFF + boff + np * (16 * 80) + k16 * 32;
                ldx4(bh[np], bd);
                ldx4(bl[np], bd + B_LO);
            }
            #pragma unroll
            for (int mt = 0; mt < 2; mt++) {
                #pragma unroll
                for (int nt = 0; nt < 6; nt++) {
                    const int np = nt >> 1, sel = (nt & 1) * 2;
                    mma_bf16(c[mt][nt], ah[mt], bh[np][sel], bh[np][sel + 1]);
                    mma_bf16(c[mt][nt], ah[mt], bl[np][sel], bl[np][sel + 1]);
                    mma_bf16(c[mt][nt], al[mt], bh[np][sel], bh[np][sel + 1]);
                }
            }
        }

        if (ch + 2 < 32)
            ldg_a(x, m0, ch + 2, tid, areg);   // registers only; no hazard

        __syncthreads();   // compute reads of buf(ch) B done before cp overwrites

        if (ch + 2 < 32) {
            stage_b(smb + (ch & 1) * BUFSZ, ch + 2, tid);
            CP_COMMIT();
        }
    }

    // Epilogue: fp16 q/k/v (q scaled by 1/32)
    #pragma unroll
    for (int mt = 0; mt < 2; mt++) {
        const int row = m0 + wr * 32 + mt * 16 + (lane >> 2);
        #pragma unroll
        for (int nt = 0; nt < 6; nt++) {
            const int ng  = wc * 48 + nt * 8;
            const int mat = ng >> 6;
            const int col = (ng & 63) + 2 * (lane & 3);
            __half* dh = (mat == 0) ? g_kh : ((mat == 1) ? g_qh : g_vh);
            const float s = (mat == 1) ? 0.03125f : 1.0f;
            *(uint32_t*)&dh[(size_t)row * 64 + col] =
                packh(c[mt][nt][0] * s, c[mt][nt][1] * s);
            *(uint32_t*)&dh[(size_t)(row + 8) * 64 + col] =
                packh(c[mt][nt][2] * s, c[mt][nt][3] * s);
        }
    }
}

// ---------------------------------------------------------------------------
// Tensor-core split-K causal attention — pure fp16 operands, fp32 accum.
// grid = (NCH, NQT, B), block = 128 (4 warps x 16 queries).
// smem 32KB: buf(i) @ i*16KB: K @ +0 (8KB), V @ +8KB.
// Q (8KB) overlays buf1's K region (consumed into registers before buf1 use).
// ---------------------------------------------------------------------------
#define KVBUF   16384
#define ATTN_SMEM 32768

__device__ __forceinline__ void stage_kv(uint32_t base, int b, int s0, int tid)
{
    const size_t g0 = ((size_t)(b * T) + s0) * 64;
    #pragma unroll
    for (int i = 0; i < 4; i++) {
        int idx = tid + 128 * i;
        int row = idx >> 3, q = idx & 7;
        uint32_t dst = base + row * 128 + ((q ^ (row & 7)) << 4);
        size_t src = g0 + row * 64 + q * 8;
        cp16(dst,        g_kh + src);
        cp16(dst + 8192, g_vh + src);
    }
}

__global__ void __launch_bounds__(128) attn_kernel()
{
    const int chunk = blockIdx.x;
    const int qt    = blockIdx.y;
    const int b     = blockIdx.z;

    const int kbeg = chunk * KCHUNK;
    const int klim = (qt + 1) * QTILE;
    if (kbeg >= klim) return;
    const int ntiles = min(4, (klim - kbeg) >> 6);

    extern __shared__ __align__(16) char sm[];
    const uint32_t smb = smem_u32(sm);
    const int tid  = threadIdx.x;
    const int w    = tid >> 5;
    const int lane = tid & 31;

    // stage Q into buf1 overlay + KV tile 0 into buf0
    {
        const size_t gq = ((size_t)(b * T) + qt * 64) * 64;
        #pragma unroll
        for (int i = 0; i < 4; i++) {
            int idx = tid + 128 * i;
            int row = idx >> 3, q = idx & 7;
            uint32_t dst = smb + KVBUF + row * 128 + ((q ^ (row & 7)) << 4);
            cp16(dst, g_qh + gq + row * 64 + q * 8);
        }
    }
    stage_kv(smb, b, kbeg, tid);
    CP_COMMIT();
    CP_WAIT(0);
    __syncthreads();

    // Q fragments -> registers (frees overlay)
    uint32_t qh[4][4];
    #pragma unroll
    for (int ks = 0; ks < 4; ks++) {
        int row = w * 16 + (lane & 15);
        int cg  = ks * 2 + (lane >> 4);
        ldx4(qh[ks], smb + KVBUF + row * 128 + ((cg ^ (row & 7)) << 4));
    }

    float o[8][4];
    #pragma unroll
    for (int nt = 0; nt < 8; nt++)
        #pragma unroll
        for (int e = 0; e < 4; e++) o[nt][e] = 0.f;
    float l0 = 0.f, l1 = 0.f;

    for (int kt = 0; kt < ntiles; kt++) {
        __syncthreads();
        if (kt + 1 < ntiles) {
            stage_kv(smb + ((kt + 1) & 1) * KVBUF, b, kbeg + (kt + 1) * 64, tid);
            CP_COMMIT();
            CP_WAIT(1);
        } else {
            CP_WAIT(0);
        }
        __syncthreads();

        const uint32_t base = smb + (kt & 1) * KVBUF;

        // ---- S = Q . K^T ----
        float c[8][4];
        #pragma unroll
        for (int nt = 0; nt < 8; nt++)
            #pragma unroll
            for (int e = 0; e < 4; e++) c[nt][e] = 0.f;

        #pragma unroll
        for (int nb = 0; nb < 4; nb++) {
            #pragma unroll
            for (int ks = 0; ks < 4; ks++) {
                int row = nb * 16 + (lane & 7) + ((lane >> 4) << 3);
                int cg  = ks * 2 + ((lane >> 3) & 1);
                uint32_t bh[4];
                ldx4(bh, base + row * 128 + ((cg ^ (row & 7)) << 4));
                mma_f16(c[2 * nb],     qh[ks], bh[0], bh[1]);
                mma_f16(c[2 * nb + 1], qh[ks], bh[2], bh[3]);
            }
        }

        // ---- exp + mask + row sums ----
        const bool diag = (kbeg + kt * 64) == qt * 64;
        const int trow = w * 16 + (lane >> 2);
        #pragma unroll
        for (int nt = 0; nt < 8; nt++) {
            const int s0l = nt * 8 + ((lane & 3) << 1);
            float p0, p1, p2, p3;
            if (diag) {
                p0 = (s0l     <= trow)     ? __expf(c[nt][0]) : 0.f;
                p1 = (s0l + 1 <= trow)     ? __expf(c[nt][1]) : 0.f;
                p2 = (s0l     <= trow + 8) ? __expf(c[nt][2]) : 0.f;
                p3 = (s0l + 1 <= trow + 8) ? __expf(c[nt][3]) : 0.f;
            } else {
                p0 = __expf(c[nt][0]);
                p1 = __expf(c[nt][1]);
                p2 = __expf(c[nt][2]);
                p3 = __expf(c[nt][3]);
            }
            l0 += p0 + p1;
            l1 += p2 + p3;
            c[nt][0] = p0; c[nt][1] = p1; c[nt][2] = p2; c[nt][3] = p3;
        }

        // ---- O += P . V ----
        #pragma unroll
        for (int ks = 0; ks < 4; ks++) {
            uint32_t pa[4];
            pa[0] = packh(c[2 * ks][0],     c[2 * ks][1]);
            pa[1] = packh(c[2 * ks][2],     c[2 * ks][3]);
            pa[2] = packh(c[2 * ks + 1][0], c[2 * ks + 1][1]);
            pa[3] = packh(c[2 * ks + 1][2], c[2 * ks + 1][3]);
            #pragma unroll
            for (int hb = 0; hb < 4; hb++) {
                int vrow = ks * 16 + (lane & 15);
                int cg   = hb * 2 + (lane >> 4);
                uint32_t vh[4];
                ldx4t(vh, base + 8192 + vrow * 128 + ((cg ^ (vrow & 7)) << 4));
                mma_f16(o[2 * hb],     pa, vh[0], vh[1]);
                mma_f16(o[2 * hb + 1], pa, vh[2], vh[3]);
            }
        }
    }

    // ---- reduce l across quads, write partials ----
    l0 += __shfl_xor_sync(0xffffffffu, l0, 1);
    l0 += __shfl_xor_sync(0xffffffffu, l0, 2);
    l1 += __shfl_xor_sync(0xffffffffu, l1, 1);
    l1 += __shfl_xor_sync(0xffffffffu, l1, 2);

    const size_t pq = (((size_t)(b * NQT + qt)) * NCH + chunk) * 64;
    const int row = w * 16 + (lane >> 2);
    #pragma unroll
    for (int nt = 0; nt < 8; nt++) {
        const int col = nt * 8 + ((lane & 3) << 1);
        float2 w0; w0.x = o[nt][0]; w0.y = o[nt][1];
        float2 w1; w1.x = o[nt][2]; w1.y = o[nt][3];
        *(float2*)&g_pacc[(pq + row) * 64 + col]     = w0;
        *(float2*)&g_pacc[(pq + row + 8) * 64 + col] = w1;
    }
    if ((lane & 3) == 0) {
        g_pl[pq + row]     = l0;
        g_pl[pq + row + 8] = l1;
    }
}

// ---------------------------------------------------------------------------
// combine split-K partials
// ---------------------------------------------------------------------------
__global__ void __launch_bounds__(256) combine_kernel(float* __restrict__ out)
{
    const int b  = blockIdx.y;
    const int th = blockIdx.x * 256 + threadIdx.x;
    const int t  = th >> 6;
    const int h  = th & 63;
    const int qt = t >> 6;
    const int qi = t & 63;
    const int nch = (t >> 8) + 1;

    const size_t base = ((size_t)(b * NQT + qt)) * NCH;
    float a = 0.f, L = 0.f;
    for (int c = 0; c < nch; c++) {
        a += g_pacc[((base + c) * QTILE + qi) * H + h];
        L += g_pl[(base + c) * QTILE + qi];
    }
    out[((size_t)(b * T + t)) * H + h] = a / L;
}

extern "C" void kernel_launch(void* const* d_in, const int* in_sizes, int n_in,
                              void* d_out, int out_size)
{
    const float* x  = (const float*)d_in[0];
    const float* Wk = (const float*)d_in[1];
    const float* Wq = (const float*)d_in[2];
    const float* Wv = (const float*)d_in[3];

    cudaFuncSetAttribute(proj_gemm_kernel,
                         cudaFuncAttributeMaxDynamicSharedMemorySize, 2 * BUFSZ);
    cudaFuncSetAttribute(attn_kernel,
                         cudaFuncAttributeMaxDynamicSharedMemorySize, ATTN_SMEM);

    convw_kernel<<<768, 256>>>(Wk, Wq, Wv);
    proj_gemm_kernel<<<256, 256, 2 * BUFSZ>>>(x);
    attn_kernel<<<dim3(NCH, NQT, B), 128, ATTN_SMEM>>>();
    combine_kernel<<<dim3(T * H / 256, B), 256>>>((float*)d_out);
}

// round 8
// speedup vs baseline: 11.7054x; 1.4154x over previous
#include <cuda_runtime.h>
#include <cuda_fp16.h>
#include <cstdint>

#define B 8
#define T 2048
#define C 1024
#define H 64
#define QTILE 64
#define NQT   (T / QTILE)
#define KCHUNK 256
#define NCH    8

// ---------------- scratch (__device__ globals; no allocation allowed) -------
__device__ float g_pacc[B * NQT * NCH * QTILE * H];
__device__ float g_pl[B * NQT * NCH * QTILE];
__device__ __half g_wt[3 * H * C];          // W^T fp16: [192 n][1024 k]
// projected q/k/v as fp16 (q pre-scaled by log2(e)/32)
__device__ __half g_qh[B * T * H];
__device__ __half g_kh[B * T * H];
__device__ __half g_vh[B * T * H];

// ---------------- helpers ----------------------------------------------------
__device__ __forceinline__ uint32_t smem_u32(const void* p) {
    uint32_t a;
    asm("{ .reg .u64 t; cvta.to.shared.u64 t, %1; cvt.u32.u64 %0, t; }"
        : "=r"(a) : "l"(p));
    return a;
}
__device__ __forceinline__ void cp16(uint32_t saddr, const void* gptr) {
    asm volatile("cp.async.cg.shared.global [%0], [%1], 16;"
                 :: "r"(saddr), "l"(__cvta_generic_to_global(gptr)) : "memory");
}
#define CP_COMMIT() asm volatile("cp.async.commit_group;" ::: "memory")
#define CP_WAIT(n)  asm volatile("cp.async.wait_group %0;" :: "n"(n) : "memory")

__device__ __forceinline__ void ldx4(uint32_t* r, uint32_t addr) {
    asm volatile("ldmatrix.sync.aligned.m8n8.x4.shared.b16 {%0,%1,%2,%3}, [%4];"
                 : "=r"(r[0]), "=r"(r[1]), "=r"(r[2]), "=r"(r[3]) : "r"(addr));
}
__device__ __forceinline__ void ldx4t(uint32_t* r, uint32_t addr) {
    asm volatile("ldmatrix.sync.aligned.m8n8.x4.trans.shared.b16 {%0,%1,%2,%3}, [%4];"
                 : "=r"(r[0]), "=r"(r[1]), "=r"(r[2]), "=r"(r[3]) : "r"(addr));
}
__device__ __forceinline__ void mma_f16(float* c, const uint32_t* a,
                                        uint32_t b0, uint32_t b1) {
    asm volatile(
        "mma.sync.aligned.m16n8k16.row.col.f32.f16.f16.f32 "
        "{%0,%1,%2,%3}, {%4,%5,%6,%7}, {%8,%9}, {%0,%1,%2,%3};"
        : "+f"(c[0]), "+f"(c[1]), "+f"(c[2]), "+f"(c[3])
        : "r"(a[0]), "r"(a[1]), "r"(a[2]), "r"(a[3]), "r"(b0), "r"(b1));
}
__device__ __forceinline__ uint32_t packh(float lo, float hi) {
    uint32_t r;
    asm("cvt.rn.f16x2.f32 %0, %1, %2;" : "=r"(r) : "f"(hi), "f"(lo));
    return r;
}
// split two fp32 into fp16x2 hi + fp16x2 residual (x represented to ~2^-22)
__device__ __forceinline__ void split2h(float f0, float f1, uint32_t& ph, uint32_t& pl) {
    ph = packh(f0, f1);
    __half2 h = *reinterpret_cast<__half2*>(&ph);
    float2 hf = __half22float2(h);
    pl = packh(f0 - hf.x, f1 - hf.y);
}
__device__ __forceinline__ void sts8(uint32_t addr, uint32_t a, uint32_t b) {
    asm volatile("st.shared.v2.b32 [%0], {%1,%2};" :: "r"(addr), "r"(a), "r"(b) : "memory");
}
__device__ __forceinline__ float ex2f(float x) {
    float r;
    asm("ex2.approx.f32 %0, %1;" : "=f"(r) : "f"(x));
    return r;
}

// ---------------------------------------------------------------------------
// W -> transposed fp16: g_wt[(o*64+n)*1024 + k] = W_o[k][n]
// ---------------------------------------------------------------------------
__global__ void __launch_bounds__(256) convw_kernel(
    const float* __restrict__ Wk, const float* __restrict__ Wq,
    const float* __restrict__ Wv)
{
    const int idx = blockIdx.x * 256 + threadIdx.x;
    const int o = idx >> 16;
    const int n = (idx >> 10) & 63;
    const int k = idx & 1023;
    const float* W = (o == 0) ? Wk : ((o == 1) ? Wq : Wv);
    g_wt[idx] = __float2half_rn(W[k * 64 + n]);
}

// ---------------------------------------------------------------------------
// Projection GEMM (HMMA fp16, 2-term: (xh + xl) . w), x converted in-kernel.
// Block tile 64x192, warp tile 32x48, k chunk 32, double-buffered.
// smem per buffer (25600 B): Ah @0 (64*80), Al @5120, Bw @10240 (192*80)
// ---------------------------------------------------------------------------
#define BUFSZ 25600
#define A_LO  5120
#define B_OFF 10240

__device__ __forceinline__ void ldg_a(const float* __restrict__ x, int m0,
                                      int ch, int tid, float4* r)
{
    const int k0 = ch << 5;
    #pragma unroll
    for (int i = 0; i < 2; i++) {
        int idx = tid + 256 * i;
        int row = idx >> 3, q = idx & 7;
        r[i] = *(const float4*)&x[(size_t)(m0 + row) * 1024 + k0 + q * 4];
    }
}
__device__ __forceinline__ void sts_a(uint32_t base, int tid, const float4* r)
{
    #pragma unroll
    for (int i = 0; i < 2; i++) {
        int idx = tid + 256 * i;
        int row = idx >> 3, q = idx & 7;
        uint32_t ph01, pl01, ph23, pl23;
        split2h(r[i].x, r[i].y, ph01, pl01);
        split2h(r[i].z, r[i].w, ph23, pl23);
        uint32_t d = base + row * 80 + q * 8;
        sts8(d, ph01, ph23);
        sts8(d + A_LO, pl01, pl23);
    }
}
__device__ __forceinline__ void stage_b(uint32_t base, int ch, int tid)
{
    const int k0 = ch << 5;
    #pragma unroll
    for (int i = 0; i < 3; i++) {
        int idx = tid + 256 * i;        // 0..767
        int r = idx >> 2, q = idx & 3;
        cp16(base + B_OFF + r * 80 + q * 16, g_wt + (size_t)r * 1024 + k0 + q * 8);
    }
}

__global__ void __launch_bounds__(256, 2) proj_gemm_kernel(const float* __restrict__ x)
{
    extern __shared__ __align__(16) char sm[];
    const uint32_t smb = smem_u32(sm);

    const int tid  = threadIdx.x;
    const int wid  = tid >> 5;
    const int lane = tid & 31;
    const int wr   = wid >> 2;
    const int wc   = wid & 3;
    const int m0   = blockIdx.x * 64;

    float c[2][6][4];
    #pragma unroll
    for (int mt = 0; mt < 2; mt++)
        #pragma unroll
        for (int nt = 0; nt < 6; nt++)
            #pragma unroll
            for (int e = 0; e < 4; e++) c[mt][nt][e] = 0.f;

    const uint32_t aoff = (uint32_t)((wr * 32 + (lane & 15)) * 80 + (lane >> 4) * 16);
    const int bg = lane >> 3;
    const uint32_t boff = (uint32_t)((wc * 48 + (lane & 7) + (bg >> 1) * 8) * 80 + (bg & 1) * 16);

    float4 areg[2];
    ldg_a(x, m0, 0, tid, areg);
    sts_a(smb, tid, areg);
    stage_b(smb, 0, tid);
    CP_COMMIT();
    ldg_a(x, m0, 1, tid, areg);
    stage_b(smb + BUFSZ, 1, tid);
    CP_COMMIT();

    for (int ch = 0; ch < 32; ch++) {
        if (ch < 31) { CP_WAIT(1); } else { CP_WAIT(0); }
        __syncthreads();

        if (ch + 1 < 32)
            sts_a(smb + ((ch + 1) & 1) * BUFSZ, tid, areg);

        const uint32_t base = smb + (ch & 1) * BUFSZ;
        #pragma unroll
        for (int k16 = 0; k16 < 2; k16++) {
            uint32_t ah[2][4], al[2][4], bw[3][4];
            #pragma unroll
            for (int mt = 0; mt < 2; mt++) {
                uint32_t ad = base + aoff + mt * (16 * 80) + k16 * 32;
                ldx4(ah[mt], ad);
                ldx4(al[mt], ad + A_LO);
            }
            #pragma unroll
            for (int np = 0; np < 3; np++)
                ldx4(bw[np], base + B_OFF + boff + np * (16 * 80) + k16 * 32);
            #pragma unroll
            for (int mt = 0; mt < 2; mt++) {
                #pragma unroll
                for (int nt = 0; nt < 6; nt++) {
                    const int np = nt >> 1, sel = (nt & 1) * 2;
                    mma_f16(c[mt][nt], ah[mt], bw[np][sel], bw[np][sel + 1]);
                    mma_f16(c[mt][nt], al[mt], bw[np][sel], bw[np][sel + 1]);
                }
            }
        }

        if (ch + 2 < 32)
            ldg_a(x, m0, ch + 2, tid, areg);

        __syncthreads();

        if (ch + 2 < 32) {
            stage_b(smb + (ch & 1) * BUFSZ, ch + 2, tid);
            CP_COMMIT();
        }
    }

    // Epilogue: fp16 q/k/v (q scaled by log2(e)/32 so attn can use ex2 directly)
    #pragma unroll
    for (int mt = 0; mt < 2; mt++) {
        const int row = m0 + wr * 32 + mt * 16 + (lane >> 2);
        #pragma unroll
        for (int nt = 0; nt < 6; nt++) {
            const int ng  = wc * 48 + nt * 8;
            const int mat = ng >> 6;
            const int col = (ng & 63) + 2 * (lane & 3);
            __half* dh = (mat == 0) ? g_kh : ((mat == 1) ? g_qh : g_vh);
            const float s = (mat == 1) ? 0.04508422f : 1.0f;   // log2e/32
            *(uint32_t*)&dh[(size_t)row * 64 + col] =
                packh(c[mt][nt][0] * s, c[mt][nt][1] * s);
            *(uint32_t*)&dh[(size_t)(row + 8) * 64 + col] =
                packh(c[mt][nt][2] * s, c[mt][nt][3] * s);
        }
    }
}

// ---------------------------------------------------------------------------
// Tensor-core split-K causal attention — fp16 operands, fp32 accum.
// grid = (NCH, NQT, B), block = 128 (4 warps x 16 queries).
// smem 32KB: buf(i) @ i*16KB: K @ +0 (8KB), V @ +8KB.
// Q (8KB) overlays buf1's K region (consumed into registers before buf1 use).
// ---------------------------------------------------------------------------
#define KVBUF   16384
#define ATTN_SMEM 32768

__device__ __forceinline__ void stage_kv(uint32_t base, int b, int s0, int tid)
{
    const size_t g0 = ((size_t)(b * T) + s0) * 64;
    #pragma unroll
    for (int i = 0; i < 4; i++) {
        int idx = tid + 128 * i;
        int row = idx >> 3, q = idx & 7;
        uint32_t dst = base + row * 128 + ((q ^ (row & 7)) << 4);
        size_t src = g0 + row * 64 + q * 8;
        cp16(dst,        g_kh + src);
        cp16(dst + 8192, g_vh + src);
    }
}

__global__ void __launch_bounds__(128) attn_kernel()
{
    const int chunk = blockIdx.x;
    const int qt    = blockIdx.y;
    const int b     = blockIdx.z;

    const int kbeg = chunk * KCHUNK;
    const int klim = (qt + 1) * QTILE;
    if (kbeg >= klim) return;
    const int ntiles = min(4, (klim - kbeg) >> 6);

    extern __shared__ __align__(16) char sm[];
    const uint32_t smb = smem_u32(sm);
    const int tid  = threadIdx.x;
    const int w    = tid >> 5;
    const int lane = tid & 31;

    // stage Q into buf1 overlay + KV tile 0 into buf0
    {
        const size_t gq = ((size_t)(b * T) + qt * 64) * 64;
        #pragma unroll
        for (int i = 0; i < 4; i++) {
            int idx = tid + 128 * i;
            int row = idx >> 3, q = idx & 7;
            uint32_t dst = smb + KVBUF + row * 128 + ((q ^ (row & 7)) << 4);
            cp16(dst, g_qh + gq + row * 64 + q * 8);
        }
    }
    stage_kv(smb, b, kbeg, tid);
    CP_COMMIT();
    CP_WAIT(0);
    __syncthreads();

    uint32_t qh[4][4];
    #pragma unroll
    for (int ks = 0; ks < 4; ks++) {
        int row = w * 16 + (lane & 15);
        int cg  = ks * 2 + (lane >> 4);
        ldx4(qh[ks], smb + KVBUF + row * 128 + ((cg ^ (row & 7)) << 4));
    }

    float o[8][4];
    #pragma unroll
    for (int nt = 0; nt < 8; nt++)
        #pragma unroll
        for (int e = 0; e < 4; e++) o[nt][e] = 0.f;
    float l0 = 0.f, l1 = 0.f;

    for (int kt = 0; kt < ntiles; kt++) {
        __syncthreads();
        if (kt + 1 < ntiles) {
            stage_kv(smb + ((kt + 1) & 1) * KVBUF, b, kbeg + (kt + 1) * 64, tid);
            CP_COMMIT();
            CP_WAIT(1);
        } else {
            CP_WAIT(0);
        }
        __syncthreads();

        const uint32_t base = smb + (kt & 1) * KVBUF;

        // ---- S' = Q . K^T (already in log2 domain) ----
        float c[8][4];
        #pragma unroll
        for (int nt = 0; nt < 8; nt++)
            #pragma unroll
            for (int e = 0; e < 4; e++) c[nt][e] = 0.f;

        #pragma unroll
        for (int nb = 0; nb < 4; nb++) {
            #pragma unroll
            for (int ks = 0; ks < 4; ks++) {
                int row = nb * 16 + (lane & 7) + ((lane >> 4) << 3);
                int cg  = ks * 2 + ((lane >> 3) & 1);
                uint32_t bh[4];
                ldx4(bh, base + row * 128 + ((cg ^ (row & 7)) << 4));
                mma_f16(c[2 * nb],     qh[ks], bh[0], bh[1]);
                mma_f16(c[2 * nb + 1], qh[ks], bh[2], bh[3]);
            }
        }

        // ---- 2^s + mask + row sums ----
        const bool diag = (kbeg + kt * 64) == qt * 64;
        const int trow = w * 16 + (lane >> 2);
        #pragma unroll
        for (int nt = 0; nt < 8; nt++) {
            const int s0l = nt * 8 + ((lane & 3) << 1);
            float p0, p1, p2, p3;
            if (diag) {
                p0 = (s0l     <= trow)     ? ex2f(c[nt][0]) : 0.f;
                p1 = (s0l + 1 <= trow)     ? ex2f(c[nt][1]) : 0.f;
                p2 = (s0l     <= trow + 8) ? ex2f(c[nt][2]) : 0.f;
                p3 = (s0l + 1 <= trow + 8) ? ex2f(c[nt][3]) : 0.f;
            } else {
                p0 = ex2f(c[nt][0]);
                p1 = ex2f(c[nt][1]);
                p2 = ex2f(c[nt][2]);
                p3 = ex2f(c[nt][3]);
            }
            l0 += p0 + p1;
            l1 += p2 + p3;
            c[nt][0] = p0; c[nt][1] = p1; c[nt][2] = p2; c[nt][3] = p3;
        }

        // ---- O += P . V ----
        #pragma unroll
        for (int ks = 0; ks < 4; ks++) {
            uint32_t pa[4];
            pa[0] = packh(c[2 * ks][0],     c[2 * ks][1]);
            pa[1] = packh(c[2 * ks][2],     c[2 * ks][3]);
            pa[2] = packh(c[2 * ks + 1][0], c[2 * ks + 1][1]);
            pa[3] = packh(c[2 * ks + 1][2], c[2 * ks + 1][3]);
            #pragma unroll
            for (int hb = 0; hb < 4; hb++) {
                int vrow = ks * 16 + (lane & 15);
                int cg   = hb * 2 + (lane >> 4);
                uint32_t vh[4];
                ldx4t(vh, base + 8192 + vrow * 128 + ((cg ^ (vrow & 7)) << 4));
                mma_f16(o[2 * hb],     pa, vh[0], vh[1]);
                mma_f16(o[2 * hb + 1], pa, vh[2], vh[3]);
            }
        }
    }

    // ---- reduce l across quads, write partials ----
    l0 += __shfl_xor_sync(0xffffffffu, l0, 1);
    l0 += __shfl_xor_sync(0xffffffffu, l0, 2);
    l1 += __shfl_xor_sync(0xffffffffu, l1, 1);
    l1 += __shfl_xor_sync(0xffffffffu, l1, 2);

    const size_t pq = (((size_t)(b * NQT + qt)) * NCH + chunk) * 64;
    const int row = w * 16 + (lane >> 2);
    #pragma unroll
    for (int nt = 0; nt < 8; nt++) {
        const int col = nt * 8 + ((lane & 3) << 1);
        float2 w0; w0.x = o[nt][0]; w0.y = o[nt][1];
        float2 w1; w1.x = o[nt][2]; w1.y = o[nt][3];
        *(float2*)&g_pacc[(pq + row) * 64 + col]     = w0;
        *(float2*)&g_pacc[(pq + row + 8) * 64 + col] = w1;
    }
    if ((lane & 3) == 0) {
        g_pl[pq + row]     = l0;
        g_pl[pq + row + 8] = l1;
    }
}

// ---------------------------------------------------------------------------
// combine split-K partials
// ---------------------------------------------------------------------------
__global__ void __launch_bounds__(256) combine_kernel(float* __restrict__ out)
{
    const int b  = blockIdx.y;
    const int th = blockIdx.x * 256 + threadIdx.x;
    const int t  = th >> 6;
    const int h  = th & 63;
    const int qt = t >> 6;
    const int qi = t & 63;
    const int nch = (t >> 8) + 1;

    const size_t base = ((size_t)(b * NQT + qt)) * NCH;
    float a = 0.f, L = 0.f;
    for (int c = 0; c < nch; c++) {
        a += g_pacc[((base + c) * QTILE + qi) * H + h];
        L += g_pl[(base + c) * QTILE + qi];
    }
    out[((size_t)(b * T + t)) * H + h] = a / L;
}

extern "C" void kernel_launch(void* const* d_in, const int* in_sizes, int n_in,
                              void* d_out, int out_size)
{
    const float* x  = (const float*)d_in[0];
    const float* Wk = (const float*)d_in[1];
    const float* Wq = (const float*)d_in[2];
    const float* Wv = (const float*)d_in[3];

    cudaFuncSetAttribute(proj_gemm_kernel,
                         cudaFuncAttributeMaxDynamicSharedMemorySize, 2 * BUFSZ);
    cudaFuncSetAttribute(attn_kernel,
                         cudaFuncAttributeMaxDynamicSharedMemorySize, ATTN_SMEM);

    convw_kernel<<<768, 256>>>(Wk, Wq, Wv);
    proj_gemm_kernel<<<256, 256, 2 * BUFSZ>>>(x);
    attn_kernel<<<dim3(NCH, NQT, B), 128, ATTN_SMEM>>>();
    combine_kernel<<<dim3(T * H / 256, B), 256>>>((float*)d_out);
}

// round 9
// speedup vs baseline: 14.1980x; 1.2129x over previous
#include <cuda_runtime.h>
#include <cuda_fp16.h>
#include <cstdint>

#define B 8
#define T 2048
#define C 1024
#define H 64
#define QTILE 64
#define NQT   (T / QTILE)
#define KCHUNK 256
#define NCH    8

// ---------------- scratch (__device__ globals; no allocation allowed) -------
__device__ __half g_pacc[B * NQT * NCH * QTILE * H];   // fp16 split-K partials
__device__ float  g_pl[B * NQT * NCH * QTILE];
__device__ __half g_wt[3 * H * C];          // W^T fp16: [192 n][1024 k]
// projected q/k/v as fp16 (q pre-scaled by log2(e)/32)
__device__ __half g_qh[B * T * H];
__device__ __half g_kh[B * T * H];
__device__ __half g_vh[B * T * H];

#define ONES_H2 0x3C003C00u

// ---------------- helpers ----------------------------------------------------
__device__ __forceinline__ uint32_t smem_u32(const void* p) {
    uint32_t a;
    asm("{ .reg .u64 t; cvta.to.shared.u64 t, %1; cvt.u32.u64 %0, t; }"
        : "=r"(a) : "l"(p));
    return a;
}
__device__ __forceinline__ void cp16(uint32_t saddr, const void* gptr) {
    asm volatile("cp.async.cg.shared.global [%0], [%1], 16;"
                 :: "r"(saddr), "l"(__cvta_generic_to_global(gptr)) : "memory");
}
#define CP_COMMIT() asm volatile("cp.async.commit_group;" ::: "memory")
#define CP_WAIT(n)  asm volatile("cp.async.wait_group %0;" :: "n"(n) : "memory")

__device__ __forceinline__ void ldx4(uint32_t* r, uint32_t addr) {
    asm volatile("ldmatrix.sync.aligned.m8n8.x4.shared.b16 {%0,%1,%2,%3}, [%4];"
                 : "=r"(r[0]), "=r"(r[1]), "=r"(r[2]), "=r"(r[3]) : "r"(addr));
}
__device__ __forceinline__ void ldx4t(uint32_t* r, uint32_t addr) {
    asm volatile("ldmatrix.sync.aligned.m8n8.x4.trans.shared.b16 {%0,%1,%2,%3}, [%4];"
                 : "=r"(r[0]), "=r"(r[1]), "=r"(r[2]), "=r"(r[3]) : "r"(addr));
}
__device__ __forceinline__ void mma_f16(float* c, const uint32_t* a,
                                        uint32_t b0, uint32_t b1) {
    asm volatile(
        "mma.sync.aligned.m16n8k16.row.col.f32.f16.f16.f32 "
        "{%0,%1,%2,%3}, {%4,%5,%6,%7}, {%8,%9}, {%0,%1,%2,%3};"
        : "+f"(c[0]), "+f"(c[1]), "+f"(c[2]), "+f"(c[3])
        : "r"(a[0]), "r"(a[1]), "r"(a[2]), "r"(a[3]), "r"(b0), "r"(b1));
}
__device__ __forceinline__ uint32_t packh(float lo, float hi) {
    uint32_t r;
    asm("cvt.rn.f16x2.f32 %0, %1, %2;" : "=r"(r) : "f"(hi), "f"(lo));
    return r;
}
__device__ __forceinline__ uint32_t h2ex2(uint32_t x) {
    uint32_t r;
    asm("ex2.approx.f16x2 %0, %1;" : "=r"(r) : "r"(x));
    return r;
}
__device__ __forceinline__ void sts8(uint32_t addr, uint32_t a, uint32_t b) {
    asm volatile("st.shared.v2.b32 [%0], {%1,%2};" :: "r"(addr), "r"(a), "r"(b) : "memory");
}

// ---------------------------------------------------------------------------
// W -> transposed fp16 via smem transpose (coalesced LDG + coalesced STG).
// grid = 48 (3 o x 16 k-tiles), block = 256.
// ---------------------------------------------------------------------------
__global__ void __launch_bounds__(256) convw_kernel(
    const float* __restrict__ Wk, const float* __restrict__ Wq,
    const float* __restrict__ Wv)
{
    __shared__ float s[64][65];
    const int bid = blockIdx.x;
    const int o   = bid >> 4;
    const int k0  = (bid & 15) << 6;
    const int tid = threadIdx.x;
    const float* __restrict__ W = (o == 0) ? Wk : ((o == 1) ? Wq : Wv);

    #pragma unroll
    for (int i = 0; i < 4; i++) {
        int f = tid + 256 * i;          // 0..1023 float4 slots (64 rows x 16)
        int row = f >> 4, q4 = (f & 15) << 2;
        float4 v = *(const float4*)&W[(size_t)(k0 + row) * 64 + q4];
        s[row][q4 + 0] = v.x;
        s[row][q4 + 1] = v.y;
        s[row][q4 + 2] = v.z;
        s[row][q4 + 3] = v.w;
    }
    __syncthreads();

    #pragma unroll
    for (int i = 0; i < 4; i++) {
        int f = tid + 256 * i;          // 64 n x 16 k-groups
        int n = f >> 4, k = (f & 15) << 2;
        uint2 w;
        w.x = packh(s[k + 0][n], s[k + 1][n]);
        w.y = packh(s[k + 2][n], s[k + 3][n]);
        *(uint2*)&g_wt[((size_t)(o * 64 + n)) * 1024 + k0 + k] = w;
    }
}

// ---------------------------------------------------------------------------
// Projection GEMM — pure fp16 HMMA (1-term). x converted in-kernel.
// Block tile 64x192, warp tile 32x48, k chunk 32, double-buffered.
// smem per buffer (20480 B): A @0 (64*80), B @5120 (192*80)
// ---------------------------------------------------------------------------
#define BUFSZ 20480
#define B_OFF 5120

__device__ __forceinline__ void ldg_a(const float* __restrict__ x, int m0,
                                      int ch, int tid, float4* r)
{
    const int k0 = ch << 5;
    #pragma unroll
    for (int i = 0; i < 2; i++) {
        int idx = tid + 256 * i;
        int row = idx >> 3, q = idx & 7;
        r[i] = *(const float4*)&x[(size_t)(m0 + row) * 1024 + k0 + q * 4];
    }
}
__device__ __forceinline__ void sts_a(uint32_t base, int tid, const float4* r)
{
    #pragma unroll
    for (int i = 0; i < 2; i++) {
        int idx = tid + 256 * i;
        int row = idx >> 3, q = idx & 7;
        sts8(base + row * 80 + q * 8,
             packh(r[i].x, r[i].y), packh(r[i].z, r[i].w));
    }
}
__device__ __forceinline__ void stage_b(uint32_t base, int ch, int tid)
{
    const int k0 = ch << 5;
    #pragma unroll
    for (int i = 0; i < 3; i++) {
        int idx = tid + 256 * i;        // 0..767
        int r = idx >> 2, q = idx & 3;
        cp16(base + B_OFF + r * 80 + q * 16, g_wt + (size_t)r * 1024 + k0 + q * 8);
    }
}

__global__ void __launch_bounds__(256, 2) proj_gemm_kernel(const float* __restrict__ x)
{
    extern __shared__ __align__(16) char sm[];
    const uint32_t smb = smem_u32(sm);

    const int tid  = threadIdx.x;
    const int wid  = tid >> 5;
    const int lane = tid & 31;
    const int wr   = wid >> 2;
    const int wc   = wid & 3;
    const int m0   = blockIdx.x * 64;

    float c[2][6][4];
    #pragma unroll
    for (int mt = 0; mt < 2; mt++)
        #pragma unroll
        for (int nt = 0; nt < 6; nt++)
            #pragma unroll
            for (int e = 0; e < 4; e++) c[mt][nt][e] = 0.f;

    const uint32_t aoff = (uint32_t)((wr * 32 + (lane & 15)) * 80 + (lane >> 4) * 16);
    const int bg = lane >> 3;
    const uint32_t boff = (uint32_t)((wc * 48 + (lane & 7) + (bg >> 1) * 8) * 80 + (bg & 1) * 16);

    float4 areg[2];
    ldg_a(x, m0, 0, tid, areg);
    sts_a(smb, tid, areg);
    stage_b(smb, 0, tid);
    CP_COMMIT();
    ldg_a(x, m0, 1, tid, areg);
    stage_b(smb + BUFSZ, 1, tid);
    CP_COMMIT();

    for (int ch = 0; ch < 32; ch++) {
        if (ch < 31) { CP_WAIT(1); } else { CP_WAIT(0); }
        __syncthreads();

        if (ch + 1 < 32)
            sts_a(smb + ((ch + 1) & 1) * BUFSZ, tid, areg);

        const uint32_t base = smb + (ch & 1) * BUFSZ;
        #pragma unroll
        for (int k16 = 0; k16 < 2; k16++) {
            uint32_t ah[2][4], bw[3][4];
            #pragma unroll
            for (int mt = 0; mt < 2; mt++)
                ldx4(ah[mt], base + aoff + mt * (16 * 80) + k16 * 32);
            #pragma unroll
            for (int np = 0; np < 3; np++)
                ldx4(bw[np], base + B_OFF + boff + np * (16 * 80) + k16 * 32);
            #pragma unroll
            for (int mt = 0; mt < 2; mt++) {
                #pragma unroll
                for (int nt = 0; nt < 6; nt++) {
                    const int np = nt >> 1, sel = (nt & 1) * 2;
                    mma_f16(c[mt][nt], ah[mt], bw[np][sel], bw[np][sel + 1]);
                }
            }
        }

        if (ch + 2 < 32)
            ldg_a(x, m0, ch + 2, tid, areg);

        __syncthreads();

        if (ch + 2 < 32) {
            stage_b(smb + (ch & 1) * BUFSZ, ch + 2, tid);
            CP_COMMIT();
        }
    }

    // Epilogue: fp16 q/k/v (q scaled by log2(e)/32 so attn uses ex2 directly)
    #pragma unroll
    for (int mt = 0; mt < 2; mt++) {
        const int row = m0 + wr * 32 + mt * 16 + (lane >> 2);
        #pragma unroll
        for (int nt = 0; nt < 6; nt++) {
            const int ng  = wc * 48 + nt * 8;
            const int mat = ng >> 6;
            const int col = (ng & 63) + 2 * (lane & 3);
            __half* dh = (mat == 0) ? g_kh : ((mat == 1) ? g_qh : g_vh);
            const float s = (mat == 1) ? 0.04508422f : 1.0f;   // log2e/32
            *(uint32_t*)&dh[(size_t)row * 64 + col] =
                packh(c[mt][nt][0] * s, c[mt][nt][1] * s);
            *(uint32_t*)&dh[(size_t)(row + 8) * 64 + col] =
                packh(c[mt][nt][2] * s, c[mt][nt][3] * s);
        }
    }
}

// ---------------------------------------------------------------------------
// Tensor-core split-K causal attention — fp16 operands, fp32 accum,
// ex2.f16x2 softmax, l row-sums via mma against all-ones B.
// grid = (NCH, NQT, B), block = 128 (4 warps x 16 queries).
// smem 32KB: buf(i) @ i*16KB: K @ +0 (8KB), V @ +8KB.
// Q (8KB) overlays buf1's K region (consumed into registers before buf1 use).
// ---------------------------------------------------------------------------
#define KVBUF   16384
#define ATTN_SMEM 32768

__device__ __forceinline__ void stage_kv(uint32_t base, int b, int s0, int tid)
{
    const size_t g0 = ((size_t)(b * T) + s0) * 64;
    #pragma unroll
    for (int i = 0; i < 4; i++) {
        int idx = tid + 128 * i;
        int row = idx >> 3, q = idx & 7;
        uint32_t dst = base + row * 128 + ((q ^ (row & 7)) << 4);
        size_t src = g0 + row * 64 + q * 8;
        cp16(dst,        g_kh + src);
        cp16(dst + 8192, g_vh + src);
    }
}

__global__ void __launch_bounds__(128) attn_kernel()
{
    const int chunk = blockIdx.x;
    const int qt    = blockIdx.y;
    const int b     = blockIdx.z;

    const int kbeg = chunk * KCHUNK;
    const int klim = (qt + 1) * QTILE;
    if (kbeg >= klim) return;
    const int ntiles = min(4, (klim - kbeg) >> 6);

    extern __shared__ __align__(16) char sm[];
    const uint32_t smb = smem_u32(sm);
    const int tid  = threadIdx.x;
    const int w    = tid >> 5;
    const int lane = tid & 31;

    // stage Q into buf1 overlay + KV tile 0 into buf0
    {
        const size_t gq = ((size_t)(b * T) + qt * 64) * 64;
        #pragma unroll
        for (int i = 0; i < 4; i++) {
            int idx = tid + 128 * i;
            int row = idx >> 3, q = idx & 7;
            uint32_t dst = smb + KVBUF + row * 128 + ((q ^ (row & 7)) << 4);
            cp16(dst, g_qh + gq + row * 64 + q * 8);
        }
    }
    stage_kv(smb, b, kbeg, tid);
    CP_COMMIT();
    CP_WAIT(0);
    __syncthreads();

    uint32_t qh[4][4];
    #pragma unroll
    for (int ks = 0; ks < 4; ks++) {
        int row = w * 16 + (lane & 15);
        int cg  = ks * 2 + (lane >> 4);
        ldx4(qh[ks], smb + KVBUF + row * 128 + ((cg ^ (row & 7)) << 4));
    }

    float o[8][4];
    #pragma unroll
    for (int nt = 0; nt < 8; nt++)
        #pragma unroll
        for (int e = 0; e < 4; e++) o[nt][e] = 0.f;
    float lsum[4] = {0.f, 0.f, 0.f, 0.f};

    for (int kt = 0; kt < ntiles; kt++) {
        __syncthreads();
        if (kt + 1 < ntiles) {
            stage_kv(smb + ((kt + 1) & 1) * KVBUF, b, kbeg + (kt + 1) * 64, tid);
            CP_COMMIT();
            CP_WAIT(1);
        } else {
            CP_WAIT(0);
        }
        __syncthreads();

        const uint32_t base = smb + (kt & 1) * KVBUF;

        // ---- S' = Q . K^T (log2 domain) ----
        float c[8][4];
        #pragma unroll
        for (int nt = 0; nt < 8; nt++)
            #pragma unroll
            for (int e = 0; e < 4; e++) c[nt][e] = 0.f;

        #pragma unroll
        for (int nb = 0; nb < 4; nb++) {
            #pragma unroll
            for (int ks = 0; ks < 4; ks++) {
                int row = nb * 16 + (lane & 7) + ((lane >> 4) << 3);
                int cg  = ks * 2 + ((lane >> 3) & 1);
                uint32_t bh[4];
                ldx4(bh, base + row * 128 + ((cg ^ (row & 7)) << 4));
                mma_f16(c[2 * nb],     qh[ks], bh[0], bh[1]);
                mma_f16(c[2 * nb + 1], qh[ks], bh[2], bh[3]);
            }
        }

        // ---- pack, 2^s in f16x2, mask ----
        const bool diag = (kbeg + kt * 64) == qt * 64;
        const int trow = w * 16 + (lane >> 2);
        uint32_t ph[8][2];
        #pragma unroll
        for (int nt = 0; nt < 8; nt++) {
            uint32_t p01 = h2ex2(packh(c[nt][0], c[nt][1]));
            uint32_t p23 = h2ex2(packh(c[nt][2], c[nt][3]));
            if (diag) {
                const int s0l = nt * 8 + ((lane & 3) << 1);
                uint32_t m01 = (s0l + 1 <= trow) ? 0xFFFFFFFFu
                             : ((s0l <= trow) ? 0x0000FFFFu : 0u);
                uint32_t m23 = (s0l + 1 <= trow + 8) ? 0xFFFFFFFFu
                             : ((s0l <= trow + 8) ? 0x0000FFFFu : 0u);
                p01 &= m01;
                p23 &= m23;
            }
            ph[nt][0] = p01;
            ph[nt][1] = p23;
        }

        // ---- O += P . V ;  l += P . 1 (tensor-core row sums) ----
        #pragma unroll
        for (int ks = 0; ks < 4; ks++) {
            uint32_t pa[4];
            pa[0] = ph[2 * ks][0];
            pa[1] = ph[2 * ks][1];
            pa[2] = ph[2 * ks + 1][0];
            pa[3] = ph[2 * ks + 1][1];
            mma_f16(lsum, pa, ONES_H2, ONES_H2);
            #pragma unroll
            for (int hb = 0; hb < 4; hb++) {
                int vrow = ks * 16 + (lane & 15);
                int cg   = hb * 2 + (lane >> 4);
                uint32_t vh[4];
                ldx4t(vh, base + 8192 + vrow * 128 + ((cg ^ (vrow & 7)) << 4));
                mma_f16(o[2 * hb],     pa, vh[0], vh[1]);
                mma_f16(o[2 * hb + 1], pa, vh[2], vh[3]);
            }
        }
    }

    // ---- write fp16 partials + fp32 l ----
    const size_t pq = (((size_t)(b * NQT + qt)) * NCH + chunk) * 64;
    const int row = w * 16 + (lane >> 2);
    #pragma unroll
    for (int nt = 0; nt < 8; nt++) {
        const int col = nt * 8 + ((lane & 3) << 1);
        *(uint32_t*)&g_pacc[(pq + row) * 64 + col]     = packh(o[nt][0], o[nt][1]);
        *(uint32_t*)&g_pacc[(pq + row + 8) * 64 + col] = packh(o[nt][2], o[nt][3]);
    }
    if ((lane & 3) == 0) {
        g_pl[pq + row]     = lsum[0];
        g_pl[pq + row + 8] = lsum[2];
    }
}

// ---------------------------------------------------------------------------
// combine split-K partials (fp16 partials, 8 h per thread).
// grid = (T*8/256, B), block = 256.
// ---------------------------------------------------------------------------
__global__ void __launch_bounds__(256) combine_kernel(float* __restrict__ out)
{
    const int b   = blockIdx.y;
    const int gid = blockIdx.x * 256 + threadIdx.x;   // 0..T*8-1
    const int t   = gid >> 3;
    const int hg  = (gid & 7) << 3;    // h group of 8
    const int qt  = t >> 6;
    const int qi  = t & 63;
    const int nch = (t >> 8) + 1;

    const size_t base = ((size_t)(b * NQT + qt)) * NCH;
    float a[8];
    #pragma unroll
    for (int j = 0; j < 8; j++) a[j] = 0.f;
    float L = 0.f;

    for (int c = 0; c < nch; c++) {
        const __half* p = &g_pacc[((base + c) * 64 + qi) * 64 + hg];
        uint4 v = *(const uint4*)p;
        float2 f0 = __half22float2(*(__half2*)&v.x);
        float2 f1 = __half22float2(*(__half2*)&v.y);
        float2 f2 = __half22float2(*(__half2*)&v.z);
        float2 f3 = __half22float2(*(__half2*)&v.w);
        a[0] += f0.x; a[1] += f0.y; a[2] += f1.x; a[3] += f1.y;
        a[4] += f2.x; a[5] += f2.y; a[6] += f3.x; a[7] += f3.y;
        L += g_pl[(base + c) * 64 + qi];
    }

    const float inv = 1.f / L;
    float4 w0, w1;
    w0.x = a[0] * inv; w0.y = a[1] * inv; w0.z = a[2] * inv; w0.w = a[3] * inv;
    w1.x = a[4] * inv; w1.y = a[5] * inv; w1.z = a[6] * inv; w1.w = a[7] * inv;
    float* op = out + ((size_t)(b * T + t)) * 64 + hg;
    *(float4*)op       = w0;
    *(float4*)(op + 4) = w1;
}

extern "C" void kernel_launch(void* const* d_in, const int* in_sizes, int n_in,
                              void* d_out, int out_size)
{
    const float* x  = (const float*)d_in[0];
    const float* Wk = (const float*)d_in[1];
    const float* Wq = (const float*)d_in[2];
    const float* Wv = (const float*)d_in[3];

    cudaFuncSetAttribute(proj_gemm_kernel,
                         cudaFuncAttributeMaxDynamicSharedMemorySize, 2 * BUFSZ);
    cudaFuncSetAttribute(attn_kernel,
                         cudaFuncAttributeMaxDynamicSharedMemorySize, ATTN_SMEM);

    convw_kernel<<<48, 256>>>(Wk, Wq, Wv);
    proj_gemm_kernel<<<256, 256, 2 * BUFSZ>>>(x);
    attn_kernel<<<dim3(NCH, NQT, B), 128, ATTN_SMEM>>>();
    combine_kernel<<<dim3(T * 8 / 256, B), 256>>>((float*)d_out);
}